// round 6
// baseline (speedup 1.0000x reference)
#include <cuda_runtime.h>
#include <cuda_bf16.h>
#include <cstdint>

// Problem constants
#define BN 8
#define CC 64
#define HH 128
#define WW 128
#define NPIX (HH * WW)

typedef unsigned long long u64;

// ---------------------------------------------------------------------------
// f32x2 packed-math helpers (dense convs)
// ---------------------------------------------------------------------------
__device__ __forceinline__ u64 pk2(float lo, float hi) {
    u64 r; asm("mov.b64 %0, {%1, %2};" : "=l"(r) : "f"(lo), "f"(hi)); return r;
}
__device__ __forceinline__ void fma2(u64& d, u64 a, u64 b) {
    asm("fma.rn.f32x2 %0, %1, %2, %0;" : "+l"(d) : "l"(a), "l"(b));
}
__device__ __forceinline__ float2 up2(u64 v) {
    float2 f; asm("mov.b64 {%0, %1}, %2;" : "=f"(f.x), "=f"(f.y) : "l"(v)); return f;
}

// ---------------------------------------------------------------------------
// mma.sync m16n8k16 bf16 (baseline ISA — works with .target sm_103)
// ---------------------------------------------------------------------------
__device__ __forceinline__ void mma16816(float& d0, float& d1, float& d2, float& d3,
                                         uint32_t a0, uint32_t a1, uint32_t a2, uint32_t a3,
                                         uint32_t b0, uint32_t b1) {
    asm volatile(
        "mma.sync.aligned.m16n8k16.row.col.f32.bf16.bf16.f32 "
        "{%0,%1,%2,%3}, {%4,%5,%6,%7}, {%8,%9}, {%0,%1,%2,%3};"
        : "+f"(d0), "+f"(d1), "+f"(d2), "+f"(d3)
        : "r"(a0), "r"(a1), "r"(a2), "r"(a3), "r"(b0), "r"(b1));
}

// ---------------------------------------------------------------------------
// Scratch (device globals — no allocation allowed in kernel_launch)
// ---------------------------------------------------------------------------
__device__ float g_x0[BN * CC * NPIX];
__device__ float g_out1[BN * CC * NPIX];
__device__ float g_out2[BN * CC * NPIX];
__device__ float g_mean[BN * CC];
__device__ float g_x2[BN * CC];
__device__ __nv_bfloat16 g_w3hi[576 * 64];
__device__ __nv_bfloat16 g_w3lo[576 * 64];

// ---------------------------------------------------------------------------
// Dense 3x3 conv, C=64 -> 64, pad 1 (f32x2 register-tiled, unchanged)
// ---------------------------------------------------------------------------
#define TILE_H 16
#define TILE_W 32
#define OCG 8
#define ICCH 8

__global__ __launch_bounds__(256) void conv3x3_dense(
    const float* __restrict__ in, const float* __restrict__ wgt,
    const float* __restrict__ bias, const float* __restrict__ res,
    float* __restrict__ outp, int add_res)
{
    __shared__ __align__(16) float ws[CC][3][3][OCG];
    __shared__ float tile[ICCH][TILE_H + 2][TILE_W + 2];

    const int tid = threadIdx.x;
    const int bw  = blockIdx.x * TILE_W;
    const int bh  = blockIdx.y * TILE_H;
    const int z   = blockIdx.z;
    const int ocg = z & 7;
    const int b   = z >> 3;

    for (int i = tid; i < CC * 9 * OCG; i += 256) {
        int o  = i & (OCG - 1);
        int r  = i / OCG;
        int k  = r % 9;
        int ic = r / 9;
        ws[ic][k / 3][k % 3][o] = wgt[((ocg * OCG + o) * CC + ic) * 9 + k];
    }

    const int tx = tid & 15;
    const int ty = tid >> 4;

    u64 a0[4], a1[4];
#pragma unroll
    for (int j = 0; j < 4; j++) { a0[j] = 0ull; a1[j] = 0ull; }

    __syncthreads();

    for (int ic0 = 0; ic0 < CC; ic0 += ICCH) {
        for (int i = tid; i < ICCH * (TILE_H + 2) * (TILE_W + 2); i += 256) {
            int xcol = i % (TILE_W + 2);
            int r2   = i / (TILE_W + 2);
            int yrow = r2 % (TILE_H + 2);
            int c    = r2 / (TILE_H + 2);
            int gh = bh + yrow - 1;
            int gw = bw + xcol - 1;
            float v = 0.f;
            if ((unsigned)gh < (unsigned)HH && (unsigned)gw < (unsigned)WW)
                v = in[((b * CC + ic0 + c) * HH + gh) * WW + gw];
            tile[c][yrow][xcol] = v;
        }
        __syncthreads();

#pragma unroll
        for (int c = 0; c < ICCH; c++) {
            const int ic = ic0 + c;
            u64 n0[4], n1[4], n2[4];
#pragma unroll
            for (int cc = 0; cc < 4; cc++) {
                float v0 = tile[c][ty + 0][tx * 2 + cc];
                float v1 = tile[c][ty + 1][tx * 2 + cc];
                float v2 = tile[c][ty + 2][tx * 2 + cc];
                n0[cc] = pk2(v0, v0);
                n1[cc] = pk2(v1, v1);
                n2[cc] = pk2(v2, v2);
            }
#pragma unroll
            for (int r = 0; r < 3; r++) {
                const u64* nr = (r == 0) ? n0 : (r == 1) ? n1 : n2;
#pragma unroll
                for (int s = 0; s < 3; s++) {
                    ulonglong2 wA = *(const ulonglong2*)&ws[ic][r][s][0];
                    ulonglong2 wB = *(const ulonglong2*)&ws[ic][r][s][4];
                    u64 v0 = nr[s];
                    u64 v1 = nr[s + 1];
                    fma2(a0[0], wA.x, v0); fma2(a0[1], wA.y, v0);
                    fma2(a0[2], wB.x, v0); fma2(a0[3], wB.y, v0);
                    fma2(a1[0], wA.x, v1); fma2(a1[1], wA.y, v1);
                    fma2(a1[2], wB.x, v1); fma2(a1[3], wB.y, v1);
                }
            }
        }
        __syncthreads();
    }

    const int h   = bh + ty;
    const int w0c = bw + tx * 2;
#pragma unroll
    for (int j = 0; j < 4; j++) {
        float2 p0 = up2(a0[j]);
        float2 p1 = up2(a1[j]);
#pragma unroll
        for (int half = 0; half < 2; half++) {
            const int oc = ocg * OCG + 2 * j + half;
            const float bb = bias[oc];
            long base = ((long)(b * CC + oc) * HH + h) * WW;
            float v0 = (half ? p0.y : p0.x) + bb;
            float v1 = (half ? p1.y : p1.x) + bb;
            if (add_res) {
                v0 += res[base + w0c];
                v1 += res[base + w0c + 1];
            }
            outp[base + w0c]     = v0;
            outp[base + w0c + 1] = v1;
        }
    }
}

// ---------------------------------------------------------------------------
// mean / eca / dw (unchanged)
// ---------------------------------------------------------------------------
__global__ __launch_bounds__(256) void mean_kernel(const float* __restrict__ x0,
                                                   float* __restrict__ mean)
{
    const int bc = blockIdx.x;
    const float4* p4 = (const float4*)(x0 + (long)bc * NPIX);
    float s = 0.f;
    for (int i = threadIdx.x; i < NPIX / 4; i += 256) {
        float4 v = p4[i];
        s += v.x + v.y + v.z + v.w;
    }
    __shared__ float red[256];
    red[threadIdx.x] = s;
    __syncthreads();
    for (int off = 128; off > 0; off >>= 1) {
        if (threadIdx.x < off) red[threadIdx.x] += red[threadIdx.x + off];
        __syncthreads();
    }
    if (threadIdx.x == 0) mean[bc] = red[0] * (1.f / (float)NPIX);
}

__global__ void eca_kernel(const float* __restrict__ mean,
                           const float* __restrict__ w2,
                           const float* __restrict__ b2,
                           float* __restrict__ x2o)
{
    const int t = threadIdx.x;
    const int b = t >> 6, c = t & 63;
    float m0 = (c > 0)  ? mean[b * CC + c - 1] : 0.f;
    float m1 =            mean[b * CC + c];
    float m2 = (c < 63) ? mean[b * CC + c + 1] : 0.f;
    x2o[t] = w2[0] * m0 + w2[1] * m1 + w2[2] * m2 + b2[0];
}

__global__ __launch_bounds__(256) void dw_kernel(
    const float* __restrict__ x0, const float* __restrict__ w1,
    const float* __restrict__ b1, const float* __restrict__ x2,
    float* __restrict__ outp)
{
    __shared__ float t[10][130];
    const int h0 = blockIdx.x * 8;
    const int c  = blockIdx.y;
    const int b  = blockIdx.z;
    const float* src = x0 + (long)(b * CC + c) * NPIX;

    for (int i = threadIdx.x; i < 10 * 130; i += 256) {
        int r = i / 130, col = i % 130;
        int gh = h0 - 1 + r, gw = col - 1;
        float v = 0.f;
        if ((unsigned)gh < (unsigned)HH && (unsigned)gw < (unsigned)WW)
            v = src[gh * WW + gw];
        t[r][col] = v;
    }
    float wk[9];
#pragma unroll
    for (int k = 0; k < 9; k++) wk[k] = w1[c * 9 + k];
    const float bb = b1[c] + x2[b * CC + c];
    __syncthreads();

    float* dst = outp + (long)(b * CC + c) * NPIX + (long)h0 * WW;
    for (int p = threadIdx.x; p < 8 * WW; p += 256) {
        int r = p / WW, wc = p % WW;
        float a = bb;
#pragma unroll
        for (int dy = 0; dy < 3; dy++)
#pragma unroll
            for (int dx = 0; dx < 3; dx++)
                a += wk[dy * 3 + dx] * t[r + dy][wc + dx];
        dst[p] = a;
    }
}

// ---------------------------------------------------------------------------
// W3 -> bf16 hi/lo prep (runs every launch; deterministic)
// ---------------------------------------------------------------------------
__global__ __launch_bounds__(256) void w3_prep(const float* __restrict__ w3,
                                               __nv_bfloat16* __restrict__ whi,
                                               __nv_bfloat16* __restrict__ wlo)
{
    int i = blockIdx.x * 256 + threadIdx.x;
    if (i < 576 * 64) {
        float v = w3[i];
        __nv_bfloat16 h = __float2bfloat16(v);
        whi[i] = h;
        wlo[i] = __float2bfloat16(v - __bfloat162float(h));
    }
}

// ---------------------------------------------------------------------------
// Dynamic conv via mma.sync bf16 hi/lo.
//   CTA = one image row (b,h): 256 threads = 8 warps, warp w owns pixels
//   [16w, 16w+16).  A [128px x 64ch] hi/lo bf16 in smem (pitch 72), fragments
//   loaded once to registers.  B = W3 [576 x 64] hi/lo from global (L1-hot),
//   in 8 chunks of 72 rows (8 channels x 9 taps).  D chunk [128 x 72] fp32 to
//   smem (pitch 73, conflict-free), then scalar apply (2 channels / pass).
// ---------------------------------------------------------------------------
#define APITCH 72                 // bf16 per A row
#define DPITCH 73                 // floats per D row
#define OFF_AHI 0                 // 128*72*2      = 18432
#define OFF_ALO 18432             // 18432
#define OFF_DSM 36864             // 128*73*4      = 37376
#define OFF_X0S 74240             // 2*3*132*4     = 3168
#define DYN_SMEM 77440

__global__ __launch_bounds__(256) void dynconv_wmma(
    const float* __restrict__ out1, const float* __restrict__ x0,
    const __nv_bfloat16* __restrict__ w3hi, const __nv_bfloat16* __restrict__ w3lo,
    const float* __restrict__ b3, float* __restrict__ out2)
{
    extern __shared__ __align__(16) char smem[];
    __nv_bfloat16* Ahi = (__nv_bfloat16*)(smem + OFF_AHI);
    __nv_bfloat16* Alo = (__nv_bfloat16*)(smem + OFF_ALO);
    float* Dsm = (float*)(smem + OFF_DSM);
    float* x0s = (float*)(smem + OFF_X0S);   // [2][3][132]

    const int tid  = threadIdx.x;
    const int warp = tid >> 5;
    const int lane = tid & 31;
    const int g    = lane >> 2;   // group id (0..7)
    const int tg   = lane & 3;    // thread-in-group
    const int h = blockIdx.x;
    const int b = blockIdx.y;

    // ---- stage A: out1[b, :, h, :] -> [p][c] bf16 hi/lo --------------------
    {
        const long base = (long)b * CC * NPIX + (long)h * WW;
        for (int i = tid; i < 128 * 32; i += 256) {
            int p  = i >> 5;        // pixel
            int cp = i & 31;        // channel pair
            float v0 = out1[base + (long)(2 * cp)     * NPIX + p];
            float v1 = out1[base + (long)(2 * cp + 1) * NPIX + p];
            __nv_bfloat16 h0 = __float2bfloat16(v0);
            __nv_bfloat16 h1 = __float2bfloat16(v1);
            __nv_bfloat16 l0 = __float2bfloat16(v0 - __bfloat162float(h0));
            __nv_bfloat16 l1 = __float2bfloat16(v1 - __bfloat162float(h1));
            *(__nv_bfloat162*)&Ahi[p * APITCH + 2 * cp] = __nv_bfloat162(h0, h1);
            *(__nv_bfloat162*)&Alo[p * APITCH + 2 * cp] = __nv_bfloat162(l0, l1);
        }
    }
    __syncthreads();

    // ---- A fragments (kept in registers for the whole kernel) --------------
    const int m0 = warp * 16;
    uint32_t Ah[4][4], Al[4][4];
#pragma unroll
    for (int k = 0; k < 4; k++) {
        int col = k * 16 + tg * 2;
        Ah[k][0] = *(const uint32_t*)&Ahi[(m0 + g)     * APITCH + col];
        Ah[k][1] = *(const uint32_t*)&Ahi[(m0 + g + 8) * APITCH + col];
        Ah[k][2] = *(const uint32_t*)&Ahi[(m0 + g)     * APITCH + col + 8];
        Ah[k][3] = *(const uint32_t*)&Ahi[(m0 + g + 8) * APITCH + col + 8];
        Al[k][0] = *(const uint32_t*)&Alo[(m0 + g)     * APITCH + col];
        Al[k][1] = *(const uint32_t*)&Alo[(m0 + g + 8) * APITCH + col];
        Al[k][2] = *(const uint32_t*)&Alo[(m0 + g)     * APITCH + col + 8];
        Al[k][3] = *(const uint32_t*)&Alo[(m0 + g + 8) * APITCH + col + 8];
    }

    // ---- 8 chunks of 8 channels (72 W3 rows) -------------------------------
    for (int q = 0; q < 8; q++) {
        float d[9][4];
#pragma unroll
        for (int j = 0; j < 9; j++)
#pragma unroll
            for (int r = 0; r < 4; r++) d[j][r] = 0.f;

        const __nv_bfloat16* Bh = w3hi + (long)(q * 72) * 64;
        const __nv_bfloat16* Bl = w3lo + (long)(q * 72) * 64;

#pragma unroll
        for (int k = 0; k < 4; k++) {
            uint32_t bh[9][2], bl[9][2];
            const int kc = k * 16 + tg * 2;
#pragma unroll
            for (int j = 0; j < 9; j++) {
                const long roff = (long)(8 * j + g) * 64 + kc;
                bh[j][0] = *(const uint32_t*)(Bh + roff);
                bh[j][1] = *(const uint32_t*)(Bh + roff + 8);
                bl[j][0] = *(const uint32_t*)(Bl + roff);
                bl[j][1] = *(const uint32_t*)(Bl + roff + 8);
            }
#pragma unroll
            for (int j = 0; j < 9; j++) {
                mma16816(d[j][0], d[j][1], d[j][2], d[j][3],
                         Ah[k][0], Ah[k][1], Ah[k][2], Ah[k][3], bh[j][0], bh[j][1]);
                mma16816(d[j][0], d[j][1], d[j][2], d[j][3],
                         Ah[k][0], Ah[k][1], Ah[k][2], Ah[k][3], bl[j][0], bl[j][1]);
                mma16816(d[j][0], d[j][1], d[j][2], d[j][3],
                         Al[k][0], Al[k][1], Al[k][2], Al[k][3], bh[j][0], bh[j][1]);
            }
        }

        __syncthreads();   // previous apply finished reading Dsm
#pragma unroll
        for (int j = 0; j < 9; j++) {
            const int col = 8 * j + tg * 2;
            Dsm[(m0 + g)     * DPITCH + col]     = d[j][0];
            Dsm[(m0 + g)     * DPITCH + col + 1] = d[j][1];
            Dsm[(m0 + g + 8) * DPITCH + col]     = d[j][2];
            Dsm[(m0 + g + 8) * DPITCH + col + 1] = d[j][3];
        }
        __syncthreads();

        // apply 8 channels, 2 at a time
        for (int pair = 0; pair < 4; pair++) {
            const int cg0 = q * 8 + pair * 2;
            for (int i = tid; i < 2 * 3 * 130; i += 256) {
                int ch  = i / 390;
                int rem = i - ch * 390;
                int r = rem / 130, j2 = rem - r * 130;
                int gh = h - 1 + r, gw = j2 - 1;
                float v = 0.f;
                if ((unsigned)gh < (unsigned)HH && (unsigned)gw < (unsigned)WW)
                    v = x0[((long)(b * CC + cg0 + ch) * HH + gh) * WW + gw];
                x0s[ch * 396 + r * 132 + j2] = v;
            }
            __syncthreads();
            {
                const int ch = tid >> 7;
                const int p  = tid & 127;
                const int cg = cg0 + ch;
                const int lc = pair * 2 + ch;
                const float* dp = &Dsm[p * DPITCH + lc * 9];
                const float* bp = b3 + cg * 9;
                const float* xs = &x0s[ch * 396];
                float s = 0.f;
#pragma unroll
                for (int k2 = 0; k2 < 9; k2++) {
                    float fil = dp[k2] + bp[k2];
                    s += fil * xs[(k2 / 3) * 132 + p + (k2 % 3)];
                }
                s = (s >= 0.f) ? s : 0.2f * s;
                out2[((long)(b * CC + cg) * HH + h) * WW + p] = s;
            }
            __syncthreads();
        }
    }
}

// ---------------------------------------------------------------------------
// Launch
// ---------------------------------------------------------------------------
extern "C" void kernel_launch(void* const* d_in, const int* in_sizes, int n_in,
                              void* d_out, int out_size)
{
    const float* x  = (const float*)d_in[0];
    const float* w0 = (const float*)d_in[1];
    const float* b0 = (const float*)d_in[2];
    const float* w1 = (const float*)d_in[3];
    const float* b1 = (const float*)d_in[4];
    const float* w2 = (const float*)d_in[5];
    const float* b2 = (const float*)d_in[6];
    const float* w3 = (const float*)d_in[7];
    const float* b3 = (const float*)d_in[8];
    const float* wf = (const float*)d_in[9];
    const float* bf = (const float*)d_in[10];
    float* out = (float*)d_out;

    float *px0, *pout1, *pout2, *pmean, *px2;
    __nv_bfloat16 *pw3hi, *pw3lo;
    cudaGetSymbolAddress((void**)&px0,   g_x0);
    cudaGetSymbolAddress((void**)&pout1, g_out1);
    cudaGetSymbolAddress((void**)&pout2, g_out2);
    cudaGetSymbolAddress((void**)&pmean, g_mean);
    cudaGetSymbolAddress((void**)&px2,   g_x2);
    cudaGetSymbolAddress((void**)&pw3hi, g_w3hi);
    cudaGetSymbolAddress((void**)&pw3lo, g_w3lo);

    cudaFuncSetAttribute(dynconv_wmma,
                         cudaFuncAttributeMaxDynamicSharedMemorySize, DYN_SMEM);

    dim3 cgrid(WW / TILE_W, HH / TILE_H, BN * (CC / OCG));

    // 0) W3 -> bf16 hi/lo
    w3_prep<<<(576 * 64 + 255) / 256, 256>>>(w3, pw3hi, pw3lo);
    // 1) conv0: x0 = conv3x3(x, w0) + b0
    conv3x3_dense<<<cgrid, 256>>>(x, w0, b0, nullptr, px0, 0);
    // 2) per-channel spatial mean of x0
    mean_kernel<<<BN * CC, 256>>>(px0, pmean);
    // 3) ECA conv1d over channel axis
    eca_kernel<<<1, BN * CC>>>(pmean, w2, b2, px2);
    // 4) out1 = depthwise3x3(x0) + b1 + x2 broadcast
    dw_kernel<<<dim3(HH / 8, CC, BN), 256>>>(px0, w1, b1, px2, pout1);
    // 5) out2 = leaky(dynamic conv), filter GEMM on tensor cores (mma.sync)
    dynconv_wmma<<<dim3(HH, BN), 256, DYN_SMEM>>>(pout1, px0, pw3hi, pw3lo, b3, pout2);
    // 6) out = conv3x3(out2, wf) + bf + x
    conv3x3_dense<<<cgrid, 256>>>(pout2, wf, bf, x, out, 1);
}

// round 7
// speedup vs baseline: 1.3926x; 1.3926x over previous
#include <cuda_runtime.h>
#include <cuda_bf16.h>
#include <cstdint>

// Problem constants
#define BN 8
#define CC 64
#define HH 128
#define WW 128
#define NPIX (HH * WW)

typedef unsigned long long u64;

// ---------------------------------------------------------------------------
// f32x2 packed-math helpers (dynconv)
// ---------------------------------------------------------------------------
__device__ __forceinline__ u64 pk2(float lo, float hi) {
    u64 r; asm("mov.b64 %0, {%1, %2};" : "=l"(r) : "f"(lo), "f"(hi)); return r;
}
__device__ __forceinline__ void fma2(u64& d, u64 a, u64 b) {
    asm("fma.rn.f32x2 %0, %1, %2, %0;" : "+l"(d) : "l"(a), "l"(b));
}
__device__ __forceinline__ u64 add2(u64 a, u64 b) {
    u64 r; asm("add.rn.f32x2 %0, %1, %2;" : "=l"(r) : "l"(a), "l"(b)); return r;
}
__device__ __forceinline__ float2 up2(u64 v) {
    float2 f; asm("mov.b64 {%0, %1}, %2;" : "=f"(f.x), "=f"(f.y) : "l"(v)); return f;
}

// ---------------------------------------------------------------------------
// mma.sync m16n8k16 bf16 (baseline ISA; fragment layout validated in R6)
// ---------------------------------------------------------------------------
__device__ __forceinline__ void mma16816(float& d0, float& d1, float& d2, float& d3,
                                         uint32_t a0, uint32_t a1, uint32_t a2, uint32_t a3,
                                         uint32_t b0, uint32_t b1) {
    asm volatile(
        "mma.sync.aligned.m16n8k16.row.col.f32.bf16.bf16.f32 "
        "{%0,%1,%2,%3}, {%4,%5,%6,%7}, {%8,%9}, {%0,%1,%2,%3};"
        : "+f"(d0), "+f"(d1), "+f"(d2), "+f"(d3)
        : "r"(a0), "r"(a1), "r"(a2), "r"(a3), "r"(b0), "r"(b1));
}

// ---------------------------------------------------------------------------
// Scratch
// ---------------------------------------------------------------------------
__device__ float g_x0[BN * CC * NPIX];
__device__ float g_out1[BN * CC * NPIX];
__device__ float g_out2[BN * CC * NPIX];
__device__ float g_mean[BN * CC];
__device__ float g_x2[BN * CC];
// Permuted conv weights, fragment order:
// [split(2: hi,lo)][stage(2)][kstep(18)][ntile(8)][lane(32)][reg(2)] u32
#define BPW_U32 (2 * 2 * 18 * 8 * 32 * 2)
__device__ uint32_t g_bpA[BPW_U32];   // w0
__device__ uint32_t g_bpF[BPW_U32];   // wf

// ---------------------------------------------------------------------------
// Weight permutation for the implicit-GEMM conv.
//   K ordering: stage (ic/32), then tap(0..8), then icl(0..31);
//   kstep t (of 18 per stage): tap = t>>1, icb = (t&1)*16.
//   reg0 packs w[oc][ic], w[oc][ic+1]; reg1 is ic+8 pair.
// ---------------------------------------------------------------------------
__global__ __launch_bounds__(256) void wconv_prep(const float* __restrict__ w,
                                                  uint32_t* __restrict__ bp)
{
    int idx = blockIdx.x * 256 + threadIdx.x;
    if (idx >= BPW_U32) return;
    int reg   = idx & 1;
    int lane  = (idx >> 1) & 31;
    int nt    = (idx >> 6) & 7;
    int r     = idx >> 9;            // ((split*2 + stage)*18 + t)
    int t     = r % 18;
    int r2    = r / 18;
    int stage = r2 & 1;
    int split = r2 >> 1;

    int tap = t >> 1;
    int icb = (t & 1) << 4;
    int tg  = lane & 3;
    int g   = lane >> 2;
    int ic  = stage * 32 + icb + 2 * tg + (reg ? 8 : 0);
    int oc  = nt * 8 + g;

    float v0 = w[(oc * CC + ic) * 9 + tap];
    float v1 = w[(oc * CC + ic + 1) * 9 + tap];
    __nv_bfloat16 h0 = __float2bfloat16(v0);
    __nv_bfloat16 h1 = __float2bfloat16(v1);
    __nv_bfloat16 e0, e1;
    if (split == 0) { e0 = h0; e1 = h1; }
    else {
        e0 = __float2bfloat16(v0 - __bfloat162float(h0));
        e1 = __float2bfloat16(v1 - __bfloat162float(h1));
    }
    __nv_bfloat162 p(e0, e1);
    bp[idx] = *(uint32_t*)&p;
}

// ---------------------------------------------------------------------------
// Dense 3x3 conv (C=64->64, pad 1) via mma.sync bf16 hi/lo implicit GEMM.
//   CTA = one output row (b,h), 256 threads = 8 warps.
//   M=128 px (warp w: m0=16w), N=64 oc (8 n-tiles), K=576 in 2 stages of 288.
//   A: smem halo S[3][130][40] bf16 (channel-contiguous, conflict-free frags).
//   B: g_bp* fragments via LDG.64 (identical across warps -> L1-hot).
// ---------------------------------------------------------------------------
#define CPAD 40
#define SELEM (3 * 130 * CPAD)            // 15600 bf16
#define CONV_SMEM (2 * SELEM * 2)         // hi + lo = 62400B

__global__ __launch_bounds__(256) void conv3x3_wmma(
    const float* __restrict__ in, const uint32_t* __restrict__ bp,
    const float* __restrict__ bias, const float* __restrict__ res,
    float* __restrict__ outp, int add_res)
{
    extern __shared__ __align__(16) char smem[];
    __nv_bfloat16* Shi = (__nv_bfloat16*)smem;
    __nv_bfloat16* Slo = Shi + SELEM;

    const int tid  = threadIdx.x;
    const int warp = tid >> 5;
    const int lane = tid & 31;
    const int g    = lane >> 2;
    const int tg   = lane & 3;
    const int m0   = warp * 16;
    const int h = blockIdx.x;
    const int b = blockIdx.y;

    float d[8][4];
#pragma unroll
    for (int n = 0; n < 8; n++)
#pragma unroll
        for (int r = 0; r < 4; r++) d[n][r] = 0.f;

    for (int stage = 0; stage < 2; stage++) {
        if (stage) __syncthreads();   // everyone done reading previous stage

        // ---- stage A halo: 32 channels -> S[ky][j][c] bf16 hi/lo ----------
        const int cs = stage * 32;
        for (int c2 = 0; c2 < 16; c2++) {
            const int c = 2 * c2;
            const float* s0 = in + ((long)(b * CC + cs + c) * HH) * WW;
            const float* s1 = s0 + (long)HH * WW;
            for (int i = tid; i < 390; i += 256) {
                int dy = i / 130, j = i - dy * 130;
                int gh = h - 1 + dy, gw = j - 1;
                float v0 = 0.f, v1 = 0.f;
                if ((unsigned)gh < (unsigned)HH && (unsigned)gw < (unsigned)WW) {
                    v0 = s0[gh * WW + gw];
                    v1 = s1[gh * WW + gw];
                }
                __nv_bfloat16 h0 = __float2bfloat16(v0);
                __nv_bfloat16 h1 = __float2bfloat16(v1);
                __nv_bfloat16 l0 = __float2bfloat16(v0 - __bfloat162float(h0));
                __nv_bfloat16 l1 = __float2bfloat16(v1 - __bfloat162float(h1));
                int e = (dy * 130 + j) * CPAD + c;
                __nv_bfloat162 ph(h0, h1), pl(l0, l1);
                *(uint32_t*)&Shi[e] = *(uint32_t*)&ph;
                *(uint32_t*)&Slo[e] = *(uint32_t*)&pl;
            }
        }
        __syncthreads();

        // ---- 18 ksteps of the GEMM ----------------------------------------
        const uint2* Bh = (const uint2*)bp + (size_t)((0 * 2 + stage) * 18) * 256;
        const uint2* Bl = (const uint2*)bp + (size_t)((1 * 2 + stage) * 18) * 256;
#pragma unroll 3
        for (int t = 0; t < 18; t++) {
            const int tap = t >> 1;
            const int icb = (t & 1) << 4;
            const int ky = tap / 3, kx = tap - 3 * ky;
            const int be = (ky * 130 + m0 + g + kx) * CPAD + icb + 2 * tg;
            uint32_t ah0 = *(const uint32_t*)&Shi[be];
            uint32_t ah1 = *(const uint32_t*)&Shi[be + 8 * CPAD];
            uint32_t ah2 = *(const uint32_t*)&Shi[be + 8];
            uint32_t ah3 = *(const uint32_t*)&Shi[be + 8 * CPAD + 8];
            uint32_t al0 = *(const uint32_t*)&Slo[be];
            uint32_t al1 = *(const uint32_t*)&Slo[be + 8 * CPAD];
            uint32_t al2 = *(const uint32_t*)&Slo[be + 8];
            uint32_t al3 = *(const uint32_t*)&Slo[be + 8 * CPAD + 8];
            const uint2* bhr = Bh + t * 256 + lane;
            const uint2* blr = Bl + t * 256 + lane;
#pragma unroll
            for (int n = 0; n < 8; n++) {
                uint2 bh = bhr[n * 32];
                uint2 bl = blr[n * 32];
                mma16816(d[n][0], d[n][1], d[n][2], d[n][3],
                         ah0, ah1, ah2, ah3, bh.x, bh.y);
                mma16816(d[n][0], d[n][1], d[n][2], d[n][3],
                         ah0, ah1, ah2, ah3, bl.x, bl.y);
                mma16816(d[n][0], d[n][1], d[n][2], d[n][3],
                         al0, al1, al2, al3, bh.x, bh.y);
            }
        }
    }

    // ---- epilogue: bias (+ residual), store --------------------------------
    const int p0 = m0 + g;
    const int p1 = p0 + 8;
#pragma unroll
    for (int n = 0; n < 8; n++) {
        const int oc = n * 8 + 2 * tg;
        const float b0v = bias[oc];
        const float b1v = bias[oc + 1];
        long base0 = ((long)(b * CC + oc) * HH + h) * WW;
        long base1 = base0 + (long)HH * WW;
        float v00 = d[n][0] + b0v;   // (p0, oc)
        float v01 = d[n][1] + b1v;   // (p0, oc+1)
        float v10 = d[n][2] + b0v;   // (p1, oc)
        float v11 = d[n][3] + b1v;   // (p1, oc+1)
        if (add_res) {
            v00 += res[base0 + p0]; v01 += res[base1 + p0];
            v10 += res[base0 + p1]; v11 += res[base1 + p1];
        }
        outp[base0 + p0] = v00;
        outp[base1 + p0] = v01;
        outp[base0 + p1] = v10;
        outp[base1 + p1] = v11;
    }
}

// ---------------------------------------------------------------------------
// mean / eca / dw (unchanged)
// ---------------------------------------------------------------------------
__global__ __launch_bounds__(256) void mean_kernel(const float* __restrict__ x0,
                                                   float* __restrict__ mean)
{
    const int bc = blockIdx.x;
    const float4* p4 = (const float4*)(x0 + (long)bc * NPIX);
    float s = 0.f;
    for (int i = threadIdx.x; i < NPIX / 4; i += 256) {
        float4 v = p4[i];
        s += v.x + v.y + v.z + v.w;
    }
    __shared__ float red[256];
    red[threadIdx.x] = s;
    __syncthreads();
    for (int off = 128; off > 0; off >>= 1) {
        if (threadIdx.x < off) red[threadIdx.x] += red[threadIdx.x + off];
        __syncthreads();
    }
    if (threadIdx.x == 0) mean[bc] = red[0] * (1.f / (float)NPIX);
}

__global__ void eca_kernel(const float* __restrict__ mean,
                           const float* __restrict__ w2,
                           const float* __restrict__ b2,
                           float* __restrict__ x2o)
{
    const int t = threadIdx.x;
    const int b = t >> 6, c = t & 63;
    float m0 = (c > 0)  ? mean[b * CC + c - 1] : 0.f;
    float m1 =            mean[b * CC + c];
    float m2 = (c < 63) ? mean[b * CC + c + 1] : 0.f;
    x2o[t] = w2[0] * m0 + w2[1] * m1 + w2[2] * m2 + b2[0];
}

__global__ __launch_bounds__(256) void dw_kernel(
    const float* __restrict__ x0, const float* __restrict__ w1,
    const float* __restrict__ b1, const float* __restrict__ x2,
    float* __restrict__ outp)
{
    __shared__ float t[10][130];
    const int h0 = blockIdx.x * 8;
    const int c  = blockIdx.y;
    const int b  = blockIdx.z;
    const float* src = x0 + (long)(b * CC + c) * NPIX;

    for (int i = threadIdx.x; i < 10 * 130; i += 256) {
        int r = i / 130, col = i % 130;
        int gh = h0 - 1 + r, gw = col - 1;
        float v = 0.f;
        if ((unsigned)gh < (unsigned)HH && (unsigned)gw < (unsigned)WW)
            v = src[gh * WW + gw];
        t[r][col] = v;
    }
    float wk[9];
#pragma unroll
    for (int k = 0; k < 9; k++) wk[k] = w1[c * 9 + k];
    const float bb = b1[c] + x2[b * CC + c];
    __syncthreads();

    float* dst = outp + (long)(b * CC + c) * NPIX + (long)h0 * WW;
    for (int p = threadIdx.x; p < 8 * WW; p += 256) {
        int r = p / WW, wc = p % WW;
        float a = bb;
#pragma unroll
        for (int dy = 0; dy < 3; dy++)
#pragma unroll
            for (int dx = 0; dx < 3; dx++)
                a += wk[dy * 3 + dx] * t[r + dy][wc + dx];
        dst[p] = a;
    }
}

// ---------------------------------------------------------------------------
// Dynamic conv, scalar f32x2 (best-known R4 version)
// ---------------------------------------------------------------------------
__global__ __launch_bounds__(256) void dynconv_kernel(
    const float* __restrict__ out1, const float* __restrict__ x0,
    const float* __restrict__ w3, const float* __restrict__ b3,
    float* __restrict__ out2)
{
    __shared__ __align__(16) float w3s[9 * 64];
    __shared__ float b3s[9];
    __shared__ float x0s[4][130];

    const int tid = threadIdx.x;
    const int tx = tid & 127;
    const int ty = tid >> 7;
    const int h0 = blockIdx.x * 2;
    const int b  = blockIdx.y;
    const int h  = h0 + ty;

    u64 ov[32];
#pragma unroll
    for (int c2 = 0; c2 < 32; c2++) {
        float lo = out1[((long)(b * CC + 2 * c2)     * HH + h) * WW + tx];
        float hi = out1[((long)(b * CC + 2 * c2 + 1) * HH + h) * WW + tx];
        ov[c2] = pk2(lo, hi);
    }

    for (int c = 0; c < CC; c++) {
        const float* w3c = w3 + (long)c * 9 * 64;
        for (int i = tid; i < 576; i += 256) w3s[i] = w3c[i];
        if (tid < 9) b3s[tid] = b3[c * 9 + tid];
        const float* x0c = x0 + (long)(b * CC + c) * NPIX;
        for (int i = tid; i < 4 * 130; i += 256) {
            int r = i / 130, j = i % 130;
            int gh = h0 - 1 + r, gw = j - 1;
            float v = 0.f;
            if ((unsigned)gh < (unsigned)HH && (unsigned)gw < (unsigned)WW)
                v = x0c[gh * WW + gw];
            x0s[r][j] = v;
        }
        __syncthreads();

        float s = 0.f;
#pragma unroll
        for (int k = 0; k < 9; k++) {
            const ulonglong2* wp = (const ulonglong2*)&w3s[k * 64];
            u64 q0 = 0ull, q1 = 0ull, q2 = 0ull, q3 = 0ull;
#pragma unroll
            for (int j = 0; j < 8; j++) {
                ulonglong2 wv0 = wp[2 * j];
                ulonglong2 wv1 = wp[2 * j + 1];
                fma2(q0, wv0.x, ov[4 * j + 0]);
                fma2(q1, wv0.y, ov[4 * j + 1]);
                fma2(q2, wv1.x, ov[4 * j + 2]);
                fma2(q3, wv1.y, ov[4 * j + 3]);
            }
            float2 p = up2(add2(add2(q0, q1), add2(q2, q3)));
            float a = b3s[k] + p.x + p.y;
            const int dy = k / 3, dx = k % 3;
            s += a * x0s[ty + dy][tx + dx];
        }
        s = (s >= 0.f) ? s : 0.2f * s;
        out2[((long)(b * CC + c) * HH + h) * WW + tx] = s;
        __syncthreads();
    }
}

// ---------------------------------------------------------------------------
// Launch
// ---------------------------------------------------------------------------
extern "C" void kernel_launch(void* const* d_in, const int* in_sizes, int n_in,
                              void* d_out, int out_size)
{
    const float* x  = (const float*)d_in[0];
    const float* w0 = (const float*)d_in[1];
    const float* b0 = (const float*)d_in[2];
    const float* w1 = (const float*)d_in[3];
    const float* b1 = (const float*)d_in[4];
    const float* w2 = (const float*)d_in[5];
    const float* b2 = (const float*)d_in[6];
    const float* w3 = (const float*)d_in[7];
    const float* b3 = (const float*)d_in[8];
    const float* wf = (const float*)d_in[9];
    const float* bf = (const float*)d_in[10];
    float* out = (float*)d_out;

    float *px0, *pout1, *pout2, *pmean, *px2;
    uint32_t *pbpA, *pbpF;
    cudaGetSymbolAddress((void**)&px0,   g_x0);
    cudaGetSymbolAddress((void**)&pout1, g_out1);
    cudaGetSymbolAddress((void**)&pout2, g_out2);
    cudaGetSymbolAddress((void**)&pmean, g_mean);
    cudaGetSymbolAddress((void**)&px2,   g_x2);
    cudaGetSymbolAddress((void**)&pbpA,  g_bpA);
    cudaGetSymbolAddress((void**)&pbpF,  g_bpF);

    cudaFuncSetAttribute(conv3x3_wmma,
                         cudaFuncAttributeMaxDynamicSharedMemorySize, CONV_SMEM);

    // 0) permute conv weights into fragment order (hi/lo)
    wconv_prep<<<(BPW_U32 + 255) / 256, 256>>>(w0, pbpA);
    wconv_prep<<<(BPW_U32 + 255) / 256, 256>>>(wf, pbpF);
    // 1) conv0 on tensor cores
    conv3x3_wmma<<<dim3(HH, BN), 256, CONV_SMEM>>>(x, pbpA, b0, nullptr, px0, 0);
    // 2) per-channel spatial mean
    mean_kernel<<<BN * CC, 256>>>(px0, pmean);
    // 3) ECA conv1d over channel axis
    eca_kernel<<<1, BN * CC>>>(pmean, w2, b2, px2);
    // 4) depthwise + channel attention
    dw_kernel<<<dim3(HH / 8, CC, BN), 256>>>(px0, w1, b1, px2, pout1);
    // 5) dynamic conv (scalar f32x2)
    dynconv_kernel<<<dim3(HH / 2, BN), 256>>>(pout1, px0, w3, b3, pout2);
    // 6) final conv on tensor cores + residual
    conv3x3_wmma<<<dim3(HH, BN), 256, CONV_SMEM>>>(pout2, pbpF, bf, x, out, 1);
}

// round 8
// speedup vs baseline: 2.0716x; 1.4876x over previous
#include <cuda_runtime.h>
#include <cuda_bf16.h>
#include <cstdint>

// Problem constants
#define BN 8
#define CC 64
#define HH 128
#define WW 128
#define NPIX (HH * WW)

typedef unsigned long long u64;

// ---------------------------------------------------------------------------
// mma.sync m16n8k16 bf16 (baseline ISA; fragment layout validated R6/R7)
// ---------------------------------------------------------------------------
__device__ __forceinline__ void mma16816(float& d0, float& d1, float& d2, float& d3,
                                         uint32_t a0, uint32_t a1, uint32_t a2, uint32_t a3,
                                         uint32_t b0, uint32_t b1) {
    asm volatile(
        "mma.sync.aligned.m16n8k16.row.col.f32.bf16.bf16.f32 "
        "{%0,%1,%2,%3}, {%4,%5,%6,%7}, {%8,%9}, {%0,%1,%2,%3};"
        : "+f"(d0), "+f"(d1), "+f"(d2), "+f"(d3)
        : "r"(a0), "r"(a1), "r"(a2), "r"(a3), "r"(b0), "r"(b1));
}

// ---------------------------------------------------------------------------
// Scratch
// ---------------------------------------------------------------------------
__device__ float g_x0[BN * CC * NPIX];
__device__ float g_out1[BN * CC * NPIX];
__device__ float g_out2[BN * CC * NPIX];
__device__ float g_mean[BN * CC];
__device__ float g_x2[BN * CC];
// Permuted dense-conv weights: [split2][stage2][kstep18][ntile8][lane32][reg2] u32
#define BPW_U32 (2 * 2 * 18 * 8 * 32 * 2)
__device__ uint32_t g_bpA[BPW_U32];   // w0
__device__ uint32_t g_bpF[BPW_U32];   // wf
// Permuted W3 fragments: [split2][tap9][half2][ntile4][kstep4][lane32] uint2
#define BP3_N (2 * 9 * 2 * 4 * 4 * 32)
__device__ uint2 g_bp3[BP3_N];

// ---------------------------------------------------------------------------
// Dense-conv weight permutation (unchanged from R7)
// ---------------------------------------------------------------------------
__global__ __launch_bounds__(256) void wconv_prep(const float* __restrict__ w,
                                                  uint32_t* __restrict__ bp)
{
    int idx = blockIdx.x * 256 + threadIdx.x;
    if (idx >= BPW_U32) return;
    int reg   = idx & 1;
    int lane  = (idx >> 1) & 31;
    int nt    = (idx >> 6) & 7;
    int r     = idx >> 9;
    int t     = r % 18;
    int r2    = r / 18;
    int stage = r2 & 1;
    int split = r2 >> 1;

    int tap = t >> 1;
    int icb = (t & 1) << 4;
    int tg  = lane & 3;
    int g   = lane >> 2;
    int ic  = stage * 32 + icb + 2 * tg + (reg ? 8 : 0);
    int oc  = nt * 8 + g;

    float v0 = w[(oc * CC + ic) * 9 + tap];
    float v1 = w[(oc * CC + ic + 1) * 9 + tap];
    __nv_bfloat16 h0 = __float2bfloat16(v0);
    __nv_bfloat16 h1 = __float2bfloat16(v1);
    __nv_bfloat16 e0, e1;
    if (split == 0) { e0 = h0; e1 = h1; }
    else {
        e0 = __float2bfloat16(v0 - __bfloat162float(h0));
        e1 = __float2bfloat16(v1 - __bfloat162float(h1));
    }
    __nv_bfloat162 p(e0, e1);
    bp[idx] = *(uint32_t*)&p;
}

// ---------------------------------------------------------------------------
// W3 fragment permutation for per-tap GEMMs.
//   B tile for tap k, half hf: G[n][kk] = W3[(hf*32 + n)*9 + k][kk], n in [0,32).
//   uint2 = (b0, b1): b0 packs kk = 16*ks + 2*tg (+1), b1 same +8; n = 8*nt + g.
// ---------------------------------------------------------------------------
__global__ __launch_bounds__(256) void w3_prep_frag(const float* __restrict__ w3,
                                                    uint2* __restrict__ bp)
{
    int idx = blockIdx.x * 256 + threadIdx.x;
    if (idx >= BP3_N) return;
    int lane = idx & 31;
    int t = idx >> 5;
    int ks = t & 3;  t >>= 2;
    int nt = t & 3;  t >>= 2;
    int hf = t & 1;  t >>= 1;
    int k  = t % 9;
    int split = t / 9;

    int g  = lane >> 2;
    int tg = lane & 3;
    int cout = hf * 32 + nt * 8 + g;
    const float* row = w3 + (long)(cout * 9 + k) * 64;

    uint32_t out[2];
#pragma unroll
    for (int r = 0; r < 2; r++) {
        int kk = 16 * ks + 2 * tg + (r ? 8 : 0);
        float v0 = row[kk];
        float v1 = row[kk + 1];
        __nv_bfloat16 h0 = __float2bfloat16(v0);
        __nv_bfloat16 h1 = __float2bfloat16(v1);
        __nv_bfloat16 e0, e1;
        if (split == 0) { e0 = h0; e1 = h1; }
        else {
            e0 = __float2bfloat16(v0 - __bfloat162float(h0));
            e1 = __float2bfloat16(v1 - __bfloat162float(h1));
        }
        __nv_bfloat162 p(e0, e1);
        out[r] = *(uint32_t*)&p;
    }
    bp[idx] = make_uint2(out[0], out[1]);
}

// ---------------------------------------------------------------------------
// Dense 3x3 conv via mma.sync bf16 hi/lo implicit GEMM (R7, staging tightened)
// ---------------------------------------------------------------------------
#define CPAD 40
#define SELEM (3 * 130 * CPAD)
#define CONV_SMEM (2 * SELEM * 2)

__global__ __launch_bounds__(256) void conv3x3_wmma(
    const float* __restrict__ in, const uint32_t* __restrict__ bp,
    const float* __restrict__ bias, const float* __restrict__ res,
    float* __restrict__ outp, int add_res)
{
    extern __shared__ __align__(16) char smem[];
    __nv_bfloat16* Shi = (__nv_bfloat16*)smem;
    __nv_bfloat16* Slo = Shi + SELEM;

    const int tid  = threadIdx.x;
    const int warp = tid >> 5;
    const int lane = tid & 31;
    const int g    = lane >> 2;
    const int tg   = lane & 3;
    const int m0   = warp * 16;
    const int h = blockIdx.x;
    const int b = blockIdx.y;

    // hoisted per-element halo coordinates (elements e = dy*130 + j)
    const int e0 = tid, e1 = tid + 256;
    int gh0 = h - 1 + e0 / 130, gw0 = e0 % 130 - 1;
    int gh1 = h - 1 + e1 / 130, gw1 = e1 % 130 - 1;
    const bool a0v = (unsigned)gh0 < (unsigned)HH && (unsigned)gw0 < (unsigned)WW;
    const bool a1v = (e1 < 390) && (unsigned)gh1 < (unsigned)HH && (unsigned)gw1 < (unsigned)WW;
    const long go0 = (long)gh0 * WW + gw0;
    const long go1 = (long)gh1 * WW + gw1;

    float d[8][4];
#pragma unroll
    for (int n = 0; n < 8; n++)
#pragma unroll
        for (int r = 0; r < 4; r++) d[n][r] = 0.f;

    for (int stage = 0; stage < 2; stage++) {
        if (stage) __syncthreads();

        const int cs = stage * 32;
        const float* pl = in + (long)(b * CC + cs) * NPIX;
#pragma unroll 4
        for (int c2 = 0; c2 < 16; c2++) {
            float f00 = a0v ? pl[go0] : 0.f;
            float f10 = a0v ? pl[NPIX + go0] : 0.f;
            __nv_bfloat16 h00 = __float2bfloat16(f00);
            __nv_bfloat16 h10 = __float2bfloat16(f10);
            __nv_bfloat16 l00 = __float2bfloat16(f00 - __bfloat162float(h00));
            __nv_bfloat16 l10 = __float2bfloat16(f10 - __bfloat162float(h10));
            __nv_bfloat162 ph0(h00, h10), pl0(l00, l10);
            *(uint32_t*)&Shi[e0 * CPAD + 2 * c2] = *(uint32_t*)&ph0;
            *(uint32_t*)&Slo[e0 * CPAD + 2 * c2] = *(uint32_t*)&pl0;
            if (e1 < 390) {
                float f01 = a1v ? pl[go1] : 0.f;
                float f11 = a1v ? pl[NPIX + go1] : 0.f;
                __nv_bfloat16 h01 = __float2bfloat16(f01);
                __nv_bfloat16 h11 = __float2bfloat16(f11);
                __nv_bfloat16 l01 = __float2bfloat16(f01 - __bfloat162float(h01));
                __nv_bfloat16 l11 = __float2bfloat16(f11 - __bfloat162float(h11));
                __nv_bfloat162 ph1(h01, h11), pl1(l01, l11);
                *(uint32_t*)&Shi[e1 * CPAD + 2 * c2] = *(uint32_t*)&ph1;
                *(uint32_t*)&Slo[e1 * CPAD + 2 * c2] = *(uint32_t*)&pl1;
            }
            pl += 2 * NPIX;
        }
        __syncthreads();

        const uint2* Bh = (const uint2*)bp + (size_t)((0 * 2 + stage) * 18) * 256;
        const uint2* Bl = (const uint2*)bp + (size_t)((1 * 2 + stage) * 18) * 256;
#pragma unroll 3
        for (int t = 0; t < 18; t++) {
            const int tap = t >> 1;
            const int icb = (t & 1) << 4;
            const int ky = tap / 3, kx = tap - 3 * ky;
            const int be = (ky * 130 + m0 + g + kx) * CPAD + icb + 2 * tg;
            uint32_t ah0 = *(const uint32_t*)&Shi[be];
            uint32_t ah1 = *(const uint32_t*)&Shi[be + 8 * CPAD];
            uint32_t ah2 = *(const uint32_t*)&Shi[be + 8];
            uint32_t ah3 = *(const uint32_t*)&Shi[be + 8 * CPAD + 8];
            uint32_t al0 = *(const uint32_t*)&Slo[be];
            uint32_t al1 = *(const uint32_t*)&Slo[be + 8 * CPAD];
            uint32_t al2 = *(const uint32_t*)&Slo[be + 8];
            uint32_t al3 = *(const uint32_t*)&Slo[be + 8 * CPAD + 8];
            const uint2* bhr = Bh + t * 256 + lane;
            const uint2* blr = Bl + t * 256 + lane;
#pragma unroll
            for (int n = 0; n < 8; n++) {
                uint2 bh = bhr[n * 32];
                uint2 bl = blr[n * 32];
                mma16816(d[n][0], d[n][1], d[n][2], d[n][3],
                         ah0, ah1, ah2, ah3, bh.x, bh.y);
                mma16816(d[n][0], d[n][1], d[n][2], d[n][3],
                         ah0, ah1, ah2, ah3, bl.x, bl.y);
                mma16816(d[n][0], d[n][1], d[n][2], d[n][3],
                         al0, al1, al2, al3, bh.x, bh.y);
            }
        }
    }

    const int p0 = m0 + g;
    const int p1 = p0 + 8;
#pragma unroll
    for (int n = 0; n < 8; n++) {
        const int oc = n * 8 + 2 * tg;
        const float b0v = bias[oc];
        const float b1v = bias[oc + 1];
        long base0 = ((long)(b * CC + oc) * HH + h) * WW;
        long base1 = base0 + (long)HH * WW;
        float v00 = d[n][0] + b0v;
        float v01 = d[n][1] + b1v;
        float v10 = d[n][2] + b0v;
        float v11 = d[n][3] + b1v;
        if (add_res) {
            v00 += res[base0 + p0]; v01 += res[base1 + p0];
            v10 += res[base0 + p1]; v11 += res[base1 + p1];
        }
        outp[base0 + p0] = v00;
        outp[base1 + p0] = v01;
        outp[base0 + p1] = v10;
        outp[base1 + p1] = v11;
    }
}

// ---------------------------------------------------------------------------
// mean / eca / dw (unchanged)
// ---------------------------------------------------------------------------
__global__ __launch_bounds__(256) void mean_kernel(const float* __restrict__ x0,
                                                   float* __restrict__ mean)
{
    const int bc = blockIdx.x;
    const float4* p4 = (const float4*)(x0 + (long)bc * NPIX);
    float s = 0.f;
    for (int i = threadIdx.x; i < NPIX / 4; i += 256) {
        float4 v = p4[i];
        s += v.x + v.y + v.z + v.w;
    }
    __shared__ float red[256];
    red[threadIdx.x] = s;
    __syncthreads();
    for (int off = 128; off > 0; off >>= 1) {
        if (threadIdx.x < off) red[threadIdx.x] += red[threadIdx.x + off];
        __syncthreads();
    }
    if (threadIdx.x == 0) mean[bc] = red[0] * (1.f / (float)NPIX);
}

__global__ void eca_kernel(const float* __restrict__ mean,
                           const float* __restrict__ w2,
                           const float* __restrict__ b2,
                           float* __restrict__ x2o)
{
    const int t = threadIdx.x;
    const int b = t >> 6, c = t & 63;
    float m0 = (c > 0)  ? mean[b * CC + c - 1] : 0.f;
    float m1 =            mean[b * CC + c];
    float m2 = (c < 63) ? mean[b * CC + c + 1] : 0.f;
    x2o[t] = w2[0] * m0 + w2[1] * m1 + w2[2] * m2 + b2[0];
}

__global__ __launch_bounds__(256) void dw_kernel(
    const float* __restrict__ x0, const float* __restrict__ w1,
    const float* __restrict__ b1, const float* __restrict__ x2,
    float* __restrict__ outp)
{
    __shared__ float t[10][130];
    const int h0 = blockIdx.x * 8;
    const int c  = blockIdx.y;
    const int b  = blockIdx.z;
    const float* src = x0 + (long)(b * CC + c) * NPIX;

    for (int i = threadIdx.x; i < 10 * 130; i += 256) {
        int r = i / 130, col = i % 130;
        int gh = h0 - 1 + r, gw = col - 1;
        float v = 0.f;
        if ((unsigned)gh < (unsigned)HH && (unsigned)gw < (unsigned)WW)
            v = src[gh * WW + gw];
        t[r][col] = v;
    }
    float wk[9];
#pragma unroll
    for (int k = 0; k < 9; k++) wk[k] = w1[c * 9 + k];
    const float bb = b1[c] + x2[b * CC + c];
    __syncthreads();

    float* dst = outp + (long)(b * CC + c) * NPIX + (long)h0 * WW;
    for (int p = threadIdx.x; p < 8 * WW; p += 256) {
        int r = p / WW, wc = p % WW;
        float a = bb;
#pragma unroll
        for (int dy = 0; dy < 3; dy++)
#pragma unroll
            for (int dx = 0; dx < 3; dx++)
                a += wk[dy * 3 + dx] * t[r + dy][wc + dx];
        dst[p] = a;
    }
}

// ---------------------------------------------------------------------------
// Dynamic conv via per-tap GEMMs: out2 = leaky( sum_k (G_k @ out1 + b3_k) .* shift_k(x0) )
//   CTA = one row (b,h), 256 threads = 8 warps.
//   A = out1 row [128px x 64] bf16 hi/lo fragments in registers (K=64).
//   Per half (32 out-channels): stage x0 halo [3][32][132], then for each tap:
//   12 MMAs -> d (1:1 thread-owned (pixel,channel)) -> fold into 16 reg accums.
//   Zero barriers inside the tap loop.
// ---------------------------------------------------------------------------
#define APITCH 72
#define DOFF_AHI 0                         // 128*72*2 = 18432
#define DOFF_ALO 18432
#define DOFF_X0S 36864                     // 3*32*132*4 = 50688
#define DOFF_B3  87552                     // 576*4
#define DYN_SMEM 89856

__global__ __launch_bounds__(256) void dynconv_tap(
    const float* __restrict__ out1, const float* __restrict__ x0,
    const uint2* __restrict__ bp3, const float* __restrict__ b3,
    float* __restrict__ out2)
{
    extern __shared__ __align__(16) char smem[];
    __nv_bfloat16* Ahi = (__nv_bfloat16*)(smem + DOFF_AHI);
    __nv_bfloat16* Alo = (__nv_bfloat16*)(smem + DOFF_ALO);
    float* x0s = (float*)(smem + DOFF_X0S);   // [dy][c][j] : (dy*32+c)*132 + j
    float* b3s = (float*)(smem + DOFF_B3);

    const int tid  = threadIdx.x;
    const int warp = tid >> 5;
    const int lane = tid & 31;
    const int g    = lane >> 2;
    const int tg   = lane & 3;
    const int m0   = warp * 16;
    const int h = blockIdx.x;
    const int b = blockIdx.y;

    // ---- stage A: out1[b,:,h,:] -> [p][c] bf16 hi/lo -----------------------
    {
        const long base = (long)b * CC * NPIX + (long)h * WW;
        for (int i = tid; i < 128 * 32; i += 256) {
            int p  = i >> 5;
            int cp = i & 31;
            float v0 = out1[base + (long)(2 * cp)     * NPIX + p];
            float v1 = out1[base + (long)(2 * cp + 1) * NPIX + p];
            __nv_bfloat16 h0 = __float2bfloat16(v0);
            __nv_bfloat16 h1 = __float2bfloat16(v1);
            __nv_bfloat16 l0 = __float2bfloat16(v0 - __bfloat162float(h0));
            __nv_bfloat16 l1 = __float2bfloat16(v1 - __bfloat162float(h1));
            __nv_bfloat162 ph(h0, h1), plp(l0, l1);
            *(uint32_t*)&Ahi[p * APITCH + 2 * cp] = *(uint32_t*)&ph;
            *(uint32_t*)&Alo[p * APITCH + 2 * cp] = *(uint32_t*)&plp;
        }
        for (int i = tid; i < 576; i += 256) b3s[i] = b3[i];
    }
    __syncthreads();

    // ---- A fragments in registers -----------------------------------------
    uint32_t Ah[4][4], Al[4][4];
#pragma unroll
    for (int k = 0; k < 4; k++) {
        int col = k * 16 + tg * 2;
        Ah[k][0] = *(const uint32_t*)&Ahi[(m0 + g)     * APITCH + col];
        Ah[k][1] = *(const uint32_t*)&Ahi[(m0 + g + 8) * APITCH + col];
        Ah[k][2] = *(const uint32_t*)&Ahi[(m0 + g)     * APITCH + col + 8];
        Ah[k][3] = *(const uint32_t*)&Ahi[(m0 + g + 8) * APITCH + col + 8];
        Al[k][0] = *(const uint32_t*)&Alo[(m0 + g)     * APITCH + col];
        Al[k][1] = *(const uint32_t*)&Alo[(m0 + g + 8) * APITCH + col];
        Al[k][2] = *(const uint32_t*)&Alo[(m0 + g)     * APITCH + col + 8];
        Al[k][3] = *(const uint32_t*)&Alo[(m0 + g + 8) * APITCH + col + 8];
    }

    const int p0 = m0 + g;
    const int p1 = p0 + 8;

    for (int hf = 0; hf < 2; hf++) {
        const int cbase = hf * 32;
        __syncthreads();   // previous half done with x0s
        // ---- stage x0 halo for this half: [3][32][132] --------------------
        for (int i = tid; i < 3 * 32 * 132; i += 256) {
            int dy = i / (32 * 132);
            int r  = i - dy * (32 * 132);
            int c  = r / 132;
            int j  = r - c * 132;
            int gh = h - 1 + dy, gw = j - 1;
            float v = 0.f;
            if ((unsigned)gh < (unsigned)HH && (unsigned)gw < (unsigned)WW)
                v = x0[((long)(b * CC + cbase + c) * HH + gh) * WW + gw];
            x0s[i] = v;
        }
        __syncthreads();

        float acc[4][4];
#pragma unroll
        for (int n = 0; n < 4; n++)
#pragma unroll
            for (int r = 0; r < 4; r++) acc[n][r] = 0.f;

#pragma unroll
        for (int k = 0; k < 9; k++) {
            const int dy = k / 3, dx = k - 3 * dy;
            const uint2* Bh = bp3 + (size_t)((0 * 9 + k) * 2 + hf) * 512 + lane;
            const uint2* Bl = bp3 + (size_t)((1 * 9 + k) * 2 + hf) * 512 + lane;
#pragma unroll
            for (int n = 0; n < 4; n++) {
                float d0 = 0.f, d1 = 0.f, d2 = 0.f, d3 = 0.f;
#pragma unroll
                for (int ks = 0; ks < 4; ks++) {
                    uint2 bh = Bh[(n * 4 + ks) * 32];
                    uint2 bl = Bl[(n * 4 + ks) * 32];
                    mma16816(d0, d1, d2, d3, Ah[ks][0], Ah[ks][1], Ah[ks][2], Ah[ks][3], bh.x, bh.y);
                    mma16816(d0, d1, d2, d3, Ah[ks][0], Ah[ks][1], Ah[ks][2], Ah[ks][3], bl.x, bl.y);
                    mma16816(d0, d1, d2, d3, Al[ks][0], Al[ks][1], Al[ks][2], Al[ks][3], bh.x, bh.y);
                }
                const int cl = n * 8 + 2 * tg;            // local channel (0..31)
                const float bb0 = b3s[(cbase + cl) * 9 + k];
                const float bb1 = b3s[(cbase + cl + 1) * 9 + k];
                const float* xr0 = &x0s[(dy * 32 + cl) * 132];
                const float* xr1 = xr0 + 132;
                acc[n][0] += (d0 + bb0) * xr0[p0 + dx];
                acc[n][1] += (d1 + bb1) * xr1[p0 + dx];
                acc[n][2] += (d2 + bb0) * xr0[p1 + dx];
                acc[n][3] += (d3 + bb1) * xr1[p1 + dx];
            }
        }

        // ---- leaky + store -------------------------------------------------
#pragma unroll
        for (int n = 0; n < 4; n++) {
            const int c = cbase + n * 8 + 2 * tg;
            long base0 = ((long)(b * CC + c) * HH + h) * WW;
            long base1 = base0 + (long)HH * WW;
            float v00 = acc[n][0], v01 = acc[n][1], v10 = acc[n][2], v11 = acc[n][3];
            v00 = (v00 >= 0.f) ? v00 : 0.2f * v00;
            v01 = (v01 >= 0.f) ? v01 : 0.2f * v01;
            v10 = (v10 >= 0.f) ? v10 : 0.2f * v10;
            v11 = (v11 >= 0.f) ? v11 : 0.2f * v11;
            out2[base0 + p0] = v00;
            out2[base1 + p0] = v01;
            out2[base0 + p1] = v10;
            out2[base1 + p1] = v11;
        }
    }
}

// ---------------------------------------------------------------------------
// Launch
// ---------------------------------------------------------------------------
extern "C" void kernel_launch(void* const* d_in, const int* in_sizes, int n_in,
                              void* d_out, int out_size)
{
    const float* x  = (const float*)d_in[0];
    const float* w0 = (const float*)d_in[1];
    const float* b0 = (const float*)d_in[2];
    const float* w1 = (const float*)d_in[3];
    const float* b1 = (const float*)d_in[4];
    const float* w2 = (const float*)d_in[5];
    const float* b2 = (const float*)d_in[6];
    const float* w3 = (const float*)d_in[7];
    const float* b3 = (const float*)d_in[8];
    const float* wf = (const float*)d_in[9];
    const float* bf = (const float*)d_in[10];
    float* out = (float*)d_out;

    float *px0, *pout1, *pout2, *pmean, *px2;
    uint32_t *pbpA, *pbpF;
    uint2 *pbp3;
    cudaGetSymbolAddress((void**)&px0,   g_x0);
    cudaGetSymbolAddress((void**)&pout1, g_out1);
    cudaGetSymbolAddress((void**)&pout2, g_out2);
    cudaGetSymbolAddress((void**)&pmean, g_mean);
    cudaGetSymbolAddress((void**)&px2,   g_x2);
    cudaGetSymbolAddress((void**)&pbpA,  g_bpA);
    cudaGetSymbolAddress((void**)&pbpF,  g_bpF);
    cudaGetSymbolAddress((void**)&pbp3,  g_bp3);

    cudaFuncSetAttribute(conv3x3_wmma,
                         cudaFuncAttributeMaxDynamicSharedMemorySize, CONV_SMEM);
    cudaFuncSetAttribute(dynconv_tap,
                         cudaFuncAttributeMaxDynamicSharedMemorySize, DYN_SMEM);

    // 0) weight permutations
    wconv_prep<<<(BPW_U32 + 255) / 256, 256>>>(w0, pbpA);
    wconv_prep<<<(BPW_U32 + 255) / 256, 256>>>(wf, pbpF);
    w3_prep_frag<<<(BP3_N + 255) / 256, 256>>>(w3, pbp3);
    // 1) conv0 on tensor cores
    conv3x3_wmma<<<dim3(HH, BN), 256, CONV_SMEM>>>(x, pbpA, b0, nullptr, px0, 0);
    // 2) per-channel spatial mean
    mean_kernel<<<BN * CC, 256>>>(px0, pmean);
    // 3) ECA conv1d over channel axis
    eca_kernel<<<1, BN * CC>>>(pmean, w2, b2, px2);
    // 4) depthwise + channel attention
    dw_kernel<<<dim3(HH / 8, CC, BN), 256>>>(px0, w1, b1, px2, pout1);
    // 5) dynamic conv: per-tap GEMMs on tensor cores, register-fused apply
    dynconv_tap<<<dim3(HH, BN), 256, DYN_SMEM>>>(pout1, px0, pbp3, b3, pout2);
    // 6) final conv on tensor cores + residual
    conv3x3_wmma<<<dim3(HH, BN), 256, CONV_SMEM>>>(pout2, pbpF, bf, x, out, 1);
}

// round 9
// speedup vs baseline: 2.2621x; 1.0920x over previous
#include <cuda_runtime.h>
#include <cuda_bf16.h>
#include <cstdint>

// Problem constants
#define BN 8
#define CC 64
#define HH 128
#define WW 128
#define NPIX (HH * WW)

// ---------------------------------------------------------------------------
// mma.sync m16n8k16 bf16 (baseline ISA; fragment layout validated R6/R7)
// ---------------------------------------------------------------------------
__device__ __forceinline__ void mma16816(float& d0, float& d1, float& d2, float& d3,
                                         uint32_t a0, uint32_t a1, uint32_t a2, uint32_t a3,
                                         uint32_t b0, uint32_t b1) {
    asm volatile(
        "mma.sync.aligned.m16n8k16.row.col.f32.bf16.bf16.f32 "
        "{%0,%1,%2,%3}, {%4,%5,%6,%7}, {%8,%9}, {%0,%1,%2,%3};"
        : "+f"(d0), "+f"(d1), "+f"(d2), "+f"(d3)
        : "r"(a0), "r"(a1), "r"(a2), "r"(a3), "r"(b0), "r"(b1));
}

// ---------------------------------------------------------------------------
// Scratch
// ---------------------------------------------------------------------------
__device__ float g_x0[BN * CC * NPIX];
__device__ float g_out1[BN * CC * NPIX];
__device__ float g_out2[BN * CC * NPIX];
__device__ float g_mean[BN * CC];
__device__ float g_x2[BN * CC];
// Permuted dense-conv weights: [split2][stage2][kstep18][ntile8][lane32][reg2] u32
#define BPW_U32 (2 * 2 * 18 * 8 * 32 * 2)
__device__ uint32_t g_bpA[BPW_U32];   // w0
__device__ uint32_t g_bpF[BPW_U32];   // wf
// Permuted W3 fragments: [split2][tap9][half2][ntile4][kstep4][lane32] uint2
#define BP3_N (2 * 9 * 2 * 4 * 4 * 32)
__device__ uint2 g_bp3[BP3_N];

// ---------------------------------------------------------------------------
// Dense-conv weight permutation
// ---------------------------------------------------------------------------
__global__ __launch_bounds__(256) void wconv_prep(const float* __restrict__ w,
                                                  uint32_t* __restrict__ bp)
{
    int idx = blockIdx.x * 256 + threadIdx.x;
    if (idx >= BPW_U32) return;
    int reg   = idx & 1;
    int lane  = (idx >> 1) & 31;
    int nt    = (idx >> 6) & 7;
    int r     = idx >> 9;
    int t     = r % 18;
    int r2    = r / 18;
    int stage = r2 & 1;
    int split = r2 >> 1;

    int tap = t >> 1;
    int icb = (t & 1) << 4;
    int tg  = lane & 3;
    int g   = lane >> 2;
    int ic  = stage * 32 + icb + 2 * tg + (reg ? 8 : 0);
    int oc  = nt * 8 + g;

    float v0 = w[(oc * CC + ic) * 9 + tap];
    float v1 = w[(oc * CC + ic + 1) * 9 + tap];
    __nv_bfloat16 h0 = __float2bfloat16(v0);
    __nv_bfloat16 h1 = __float2bfloat16(v1);
    __nv_bfloat16 e0, e1;
    if (split == 0) { e0 = h0; e1 = h1; }
    else {
        e0 = __float2bfloat16(v0 - __bfloat162float(h0));
        e1 = __float2bfloat16(v1 - __bfloat162float(h1));
    }
    __nv_bfloat162 p(e0, e1);
    bp[idx] = *(uint32_t*)&p;
}

// ---------------------------------------------------------------------------
// W3 fragment permutation for per-tap GEMMs
// ---------------------------------------------------------------------------
__global__ __launch_bounds__(256) void w3_prep_frag(const float* __restrict__ w3,
                                                    uint2* __restrict__ bp)
{
    int idx = blockIdx.x * 256 + threadIdx.x;
    if (idx >= BP3_N) return;
    int lane = idx & 31;
    int t = idx >> 5;
    int ks = t & 3;  t >>= 2;
    int nt = t & 3;  t >>= 2;
    int hf = t & 1;  t >>= 1;
    int k  = t % 9;
    int split = t / 9;

    int g  = lane >> 2;
    int tg = lane & 3;
    int cout = hf * 32 + nt * 8 + g;
    const float* row = w3 + (long)(cout * 9 + k) * 64;

    uint32_t out[2];
#pragma unroll
    for (int r = 0; r < 2; r++) {
        int kk = 16 * ks + 2 * tg + (r ? 8 : 0);
        float v0 = row[kk];
        float v1 = row[kk + 1];
        __nv_bfloat16 h0 = __float2bfloat16(v0);
        __nv_bfloat16 h1 = __float2bfloat16(v1);
        __nv_bfloat16 e0, e1;
        if (split == 0) { e0 = h0; e1 = h1; }
        else {
            e0 = __float2bfloat16(v0 - __bfloat162float(h0));
            e1 = __float2bfloat16(v1 - __bfloat162float(h1));
        }
        __nv_bfloat162 p(e0, e1);
        out[r] = *(uint32_t*)&p;
    }
    bp[idx] = make_uint2(out[0], out[1]);
}

// ---------------------------------------------------------------------------
// Dense 3x3 conv via mma.sync bf16 hi/lo implicit GEMM.
//   CPAD=36: fragment LDS banks = (18g + tg) mod 32, all 32 distinct.
//   launch_bounds(256,4): 56.2KB smem x4 + <=64 regs -> 4 CTAs/SM.
// ---------------------------------------------------------------------------
#define CPAD 36
#define SELEM (3 * 130 * CPAD)
#define CONV_SMEM (2 * SELEM * 2)

__global__ __launch_bounds__(256, 4) void conv3x3_wmma(
    const float* __restrict__ in, const uint32_t* __restrict__ bp,
    const float* __restrict__ bias, const float* __restrict__ res,
    float* __restrict__ outp, int add_res)
{
    extern __shared__ __align__(16) char smem[];
    __nv_bfloat16* Shi = (__nv_bfloat16*)smem;
    __nv_bfloat16* Slo = Shi + SELEM;

    const int tid  = threadIdx.x;
    const int warp = tid >> 5;
    const int lane = tid & 31;
    const int g    = lane >> 2;
    const int tg   = lane & 3;
    const int m0   = warp * 16;
    const int h = blockIdx.x;
    const int b = blockIdx.y;

    // hoisted halo coordinates (elements e = dy*130 + j)
    const int e0 = tid, e1 = tid + 256;
    int gh0 = h - 1 + e0 / 130, gw0 = e0 % 130 - 1;
    int gh1 = h - 1 + e1 / 130, gw1 = e1 % 130 - 1;
    const bool a0v = (unsigned)gh0 < (unsigned)HH && (unsigned)gw0 < (unsigned)WW;
    const bool a1v = (e1 < 390) && (unsigned)gh1 < (unsigned)HH && (unsigned)gw1 < (unsigned)WW;
    const long go0 = (long)gh0 * WW + gw0;
    const long go1 = (long)gh1 * WW + gw1;

    float d[8][4];
#pragma unroll
    for (int n = 0; n < 8; n++)
#pragma unroll
        for (int r = 0; r < 4; r++) d[n][r] = 0.f;

    for (int stage = 0; stage < 2; stage++) {
        if (stage) __syncthreads();

        const int cs = stage * 32;
        const float* pl = in + (long)(b * CC + cs) * NPIX;
#pragma unroll 4
        for (int c2 = 0; c2 < 16; c2++) {
            float f00 = a0v ? pl[go0] : 0.f;
            float f10 = a0v ? pl[NPIX + go0] : 0.f;
            __nv_bfloat16 h00 = __float2bfloat16(f00);
            __nv_bfloat16 h10 = __float2bfloat16(f10);
            __nv_bfloat16 l00 = __float2bfloat16(f00 - __bfloat162float(h00));
            __nv_bfloat16 l10 = __float2bfloat16(f10 - __bfloat162float(h10));
            __nv_bfloat162 ph0(h00, h10), pl0(l00, l10);
            *(uint32_t*)&Shi[e0 * CPAD + 2 * c2] = *(uint32_t*)&ph0;
            *(uint32_t*)&Slo[e0 * CPAD + 2 * c2] = *(uint32_t*)&pl0;
            if (e1 < 390) {
                float f01 = a1v ? pl[go1] : 0.f;
                float f11 = a1v ? pl[NPIX + go1] : 0.f;
                __nv_bfloat16 h01 = __float2bfloat16(f01);
                __nv_bfloat16 h11 = __float2bfloat16(f11);
                __nv_bfloat16 l01 = __float2bfloat16(f01 - __bfloat162float(h01));
                __nv_bfloat16 l11 = __float2bfloat16(f11 - __bfloat162float(h11));
                __nv_bfloat162 ph1(h01, h11), pl1(l01, l11);
                *(uint32_t*)&Shi[e1 * CPAD + 2 * c2] = *(uint32_t*)&ph1;
                *(uint32_t*)&Slo[e1 * CPAD + 2 * c2] = *(uint32_t*)&pl1;
            }
            pl += 2 * NPIX;
        }
        __syncthreads();

        const uint2* Bh = (const uint2*)bp + (size_t)((0 * 2 + stage) * 18) * 256;
        const uint2* Bl = (const uint2*)bp + (size_t)((1 * 2 + stage) * 18) * 256;
#pragma unroll 3
        for (int t = 0; t < 18; t++) {
            const int tap = t >> 1;
            const int icb = (t & 1) << 4;
            const int ky = tap / 3, kx = tap - 3 * ky;
            const int be = (ky * 130 + m0 + g + kx) * CPAD + icb + 2 * tg;
            uint32_t ah0 = *(const uint32_t*)&Shi[be];
            uint32_t ah1 = *(const uint32_t*)&Shi[be + 8 * CPAD];
            uint32_t ah2 = *(const uint32_t*)&Shi[be + 8];
            uint32_t ah3 = *(const uint32_t*)&Shi[be + 8 * CPAD + 8];
            uint32_t al0 = *(const uint32_t*)&Slo[be];
            uint32_t al1 = *(const uint32_t*)&Slo[be + 8 * CPAD];
            uint32_t al2 = *(const uint32_t*)&Slo[be + 8];
            uint32_t al3 = *(const uint32_t*)&Slo[be + 8 * CPAD + 8];
            const uint2* bhr = Bh + t * 256 + lane;
            const uint2* blr = Bl + t * 256 + lane;
#pragma unroll
            for (int n = 0; n < 8; n++) {
                uint2 bh = bhr[n * 32];
                uint2 bl = blr[n * 32];
                mma16816(d[n][0], d[n][1], d[n][2], d[n][3],
                         ah0, ah1, ah2, ah3, bh.x, bh.y);
                mma16816(d[n][0], d[n][1], d[n][2], d[n][3],
                         ah0, ah1, ah2, ah3, bl.x, bl.y);
                mma16816(d[n][0], d[n][1], d[n][2], d[n][3],
                         al0, al1, al2, al3, bh.x, bh.y);
            }
        }
    }

    const int p0 = m0 + g;
    const int p1 = p0 + 8;
#pragma unroll
    for (int n = 0; n < 8; n++) {
        const int oc = n * 8 + 2 * tg;
        const float b0v = bias[oc];
        const float b1v = bias[oc + 1];
        long base0 = ((long)(b * CC + oc) * HH + h) * WW;
        long base1 = base0 + (long)HH * WW;
        float v00 = d[n][0] + b0v;
        float v01 = d[n][1] + b1v;
        float v10 = d[n][2] + b0v;
        float v11 = d[n][3] + b1v;
        if (add_res) {
            v00 += res[base0 + p0]; v01 += res[base1 + p0];
            v10 += res[base0 + p1]; v11 += res[base1 + p1];
        }
        outp[base0 + p0] = v00;
        outp[base1 + p0] = v01;
        outp[base0 + p1] = v10;
        outp[base1 + p1] = v11;
    }
}

// ---------------------------------------------------------------------------
// mean / eca / dw (unchanged)
// ---------------------------------------------------------------------------
__global__ __launch_bounds__(256) void mean_kernel(const float* __restrict__ x0,
                                                   float* __restrict__ mean)
{
    const int bc = blockIdx.x;
    const float4* p4 = (const float4*)(x0 + (long)bc * NPIX);
    float s = 0.f;
    for (int i = threadIdx.x; i < NPIX / 4; i += 256) {
        float4 v = p4[i];
        s += v.x + v.y + v.z + v.w;
    }
    __shared__ float red[256];
    red[threadIdx.x] = s;
    __syncthreads();
    for (int off = 128; off > 0; off >>= 1) {
        if (threadIdx.x < off) red[threadIdx.x] += red[threadIdx.x + off];
        __syncthreads();
    }
    if (threadIdx.x == 0) mean[bc] = red[0] * (1.f / (float)NPIX);
}

__global__ void eca_kernel(const float* __restrict__ mean,
                           const float* __restrict__ w2,
                           const float* __restrict__ b2,
                           float* __restrict__ x2o)
{
    const int t = threadIdx.x;
    const int b = t >> 6, c = t & 63;
    float m0 = (c > 0)  ? mean[b * CC + c - 1] : 0.f;
    float m1 =            mean[b * CC + c];
    float m2 = (c < 63) ? mean[b * CC + c + 1] : 0.f;
    x2o[t] = w2[0] * m0 + w2[1] * m1 + w2[2] * m2 + b2[0];
}

__global__ __launch_bounds__(256) void dw_kernel(
    const float* __restrict__ x0, const float* __restrict__ w1,
    const float* __restrict__ b1, const float* __restrict__ x2,
    float* __restrict__ outp)
{
    __shared__ float t[10][130];
    const int h0 = blockIdx.x * 8;
    const int c  = blockIdx.y;
    const int b  = blockIdx.z;
    const float* src = x0 + (long)(b * CC + c) * NPIX;

    for (int i = threadIdx.x; i < 10 * 130; i += 256) {
        int r = i / 130, col = i % 130;
        int gh = h0 - 1 + r, gw = col - 1;
        float v = 0.f;
        if ((unsigned)gh < (unsigned)HH && (unsigned)gw < (unsigned)WW)
            v = src[gh * WW + gw];
        t[r][col] = v;
    }
    float wk[9];
#pragma unroll
    for (int k = 0; k < 9; k++) wk[k] = w1[c * 9 + k];
    const float bb = b1[c] + x2[b * CC + c];
    __syncthreads();

    float* dst = outp + (long)(b * CC + c) * NPIX + (long)h0 * WW;
    for (int p = threadIdx.x; p < 8 * WW; p += 256) {
        int r = p / WW, wc = p % WW;
        float a = bb;
#pragma unroll
        for (int dy = 0; dy < 3; dy++)
#pragma unroll
            for (int dx = 0; dx < 3; dx++)
                a += wk[dy * 3 + dx] * t[r + dy][wc + dx];
        dst[p] = a;
    }
}

// ---------------------------------------------------------------------------
// Dynamic conv via per-tap GEMMs (R8 structure) with smem aliasing:
//   region [0, 50688) is first the A staging (Ahi/Alo, 36864B) and later the
//   x0 halo buffer (50688B) — A smem is dead once fragments are in registers.
//   53.0KB total + launch_bounds(256,3) -> 3 CTAs/SM.
// ---------------------------------------------------------------------------
#define APITCH 72
#define DOFF_B3  50688
#define DYN_SMEM (50688 + 2304)

__global__ __launch_bounds__(256, 3) void dynconv_tap(
    const float* __restrict__ out1, const float* __restrict__ x0,
    const uint2* __restrict__ bp3, const float* __restrict__ b3,
    float* __restrict__ out2)
{
    extern __shared__ __align__(16) char smem[];
    __nv_bfloat16* Ahi = (__nv_bfloat16*)smem;           // [0, 18432)
    __nv_bfloat16* Alo = Ahi + 128 * APITCH;             // [18432, 36864)
    float* x0s = (float*)smem;                           // aliases A region
    float* b3s = (float*)(smem + DOFF_B3);

    const int tid  = threadIdx.x;
    const int warp = tid >> 5;
    const int lane = tid & 31;
    const int g    = lane >> 2;
    const int tg   = lane & 3;
    const int m0   = warp * 16;
    const int h = blockIdx.x;
    const int b = blockIdx.y;

    // ---- stage A: out1[b,:,h,:] -> [p][c] bf16 hi/lo -----------------------
    {
        const long base = (long)b * CC * NPIX + (long)h * WW;
        for (int i = tid; i < 128 * 32; i += 256) {
            int p  = i >> 5;
            int cp = i & 31;
            float v0 = out1[base + (long)(2 * cp)     * NPIX + p];
            float v1 = out1[base + (long)(2 * cp + 1) * NPIX + p];
            __nv_bfloat16 h0 = __float2bfloat16(v0);
            __nv_bfloat16 h1 = __float2bfloat16(v1);
            __nv_bfloat16 l0 = __float2bfloat16(v0 - __bfloat162float(h0));
            __nv_bfloat16 l1 = __float2bfloat16(v1 - __bfloat162float(h1));
            __nv_bfloat162 ph(h0, h1), plp(l0, l1);
            *(uint32_t*)&Ahi[p * APITCH + 2 * cp] = *(uint32_t*)&ph;
            *(uint32_t*)&Alo[p * APITCH + 2 * cp] = *(uint32_t*)&plp;
        }
        for (int i = tid; i < 576; i += 256) b3s[i] = b3[i];
    }
    __syncthreads();

    // ---- A fragments in registers -----------------------------------------
    uint32_t Ah[4][4], Al[4][4];
#pragma unroll
    for (int k = 0; k < 4; k++) {
        int col = k * 16 + tg * 2;
        Ah[k][0] = *(const uint32_t*)&Ahi[(m0 + g)     * APITCH + col];
        Ah[k][1] = *(const uint32_t*)&Ahi[(m0 + g + 8) * APITCH + col];
        Ah[k][2] = *(const uint32_t*)&Ahi[(m0 + g)     * APITCH + col + 8];
        Ah[k][3] = *(const uint32_t*)&Ahi[(m0 + g + 8) * APITCH + col + 8];
        Al[k][0] = *(const uint32_t*)&Alo[(m0 + g)     * APITCH + col];
        Al[k][1] = *(const uint32_t*)&Alo[(m0 + g + 8) * APITCH + col];
        Al[k][2] = *(const uint32_t*)&Alo[(m0 + g)     * APITCH + col + 8];
        Al[k][3] = *(const uint32_t*)&Alo[(m0 + g + 8) * APITCH + col + 8];
    }

    const int p0 = m0 + g;
    const int p1 = p0 + 8;

    for (int hf = 0; hf < 2; hf++) {
        const int cbase = hf * 32;
        __syncthreads();   // fragments loaded / previous half done with x0s
        // ---- stage x0 halo for this half: [3][32][132] (overwrites A) -----
        for (int i = tid; i < 3 * 32 * 132; i += 256) {
            int dy = i / (32 * 132);
            int r  = i - dy * (32 * 132);
            int c  = r / 132;
            int j  = r - c * 132;
            int gh = h - 1 + dy, gw = j - 1;
            float v = 0.f;
            if ((unsigned)gh < (unsigned)HH && (unsigned)gw < (unsigned)WW)
                v = x0[((long)(b * CC + cbase + c) * HH + gh) * WW + gw];
            x0s[i] = v;
        }
        __syncthreads();

        float acc[4][4];
#pragma unroll
        for (int n = 0; n < 4; n++)
#pragma unroll
            for (int r = 0; r < 4; r++) acc[n][r] = 0.f;

#pragma unroll
        for (int k = 0; k < 9; k++) {
            const int dy = k / 3, dx = k - 3 * dy;
            const uint2* Bh = bp3 + (size_t)((0 * 9 + k) * 2 + hf) * 512 + lane;
            const uint2* Bl = bp3 + (size_t)((1 * 9 + k) * 2 + hf) * 512 + lane;
#pragma unroll
            for (int n = 0; n < 4; n++) {
                float d0 = 0.f, d1 = 0.f, d2 = 0.f, d3 = 0.f;
#pragma unroll
                for (int ks = 0; ks < 4; ks++) {
                    uint2 bh = Bh[(n * 4 + ks) * 32];
                    uint2 bl = Bl[(n * 4 + ks) * 32];
                    mma16816(d0, d1, d2, d3, Ah[ks][0], Ah[ks][1], Ah[ks][2], Ah[ks][3], bh.x, bh.y);
                    mma16816(d0, d1, d2, d3, Ah[ks][0], Ah[ks][1], Ah[ks][2], Ah[ks][3], bl.x, bl.y);
                    mma16816(d0, d1, d2, d3, Al[ks][0], Al[ks][1], Al[ks][2], Al[ks][3], bh.x, bh.y);
                }
                const int cl = n * 8 + 2 * tg;
                const float bb0 = b3s[(cbase + cl) * 9 + k];
                const float bb1 = b3s[(cbase + cl + 1) * 9 + k];
                const float* xr0 = &x0s[(dy * 32 + cl) * 132];
                const float* xr1 = xr0 + 132;
                acc[n][0] += (d0 + bb0) * xr0[p0 + dx];
                acc[n][1] += (d1 + bb1) * xr1[p0 + dx];
                acc[n][2] += (d2 + bb0) * xr0[p1 + dx];
                acc[n][3] += (d3 + bb1) * xr1[p1 + dx];
            }
        }

#pragma unroll
        for (int n = 0; n < 4; n++) {
            const int c = cbase + n * 8 + 2 * tg;
            long base0 = ((long)(b * CC + c) * HH + h) * WW;
            long base1 = base0 + (long)HH * WW;
            float v00 = acc[n][0], v01 = acc[n][1], v10 = acc[n][2], v11 = acc[n][3];
            v00 = (v00 >= 0.f) ? v00 : 0.2f * v00;
            v01 = (v01 >= 0.f) ? v01 : 0.2f * v01;
            v10 = (v10 >= 0.f) ? v10 : 0.2f * v10;
            v11 = (v11 >= 0.f) ? v11 : 0.2f * v11;
            out2[base0 + p0] = v00;
            out2[base1 + p0] = v01;
            out2[base0 + p1] = v10;
            out2[base1 + p1] = v11;
        }
    }
}

// ---------------------------------------------------------------------------
// Launch
// ---------------------------------------------------------------------------
extern "C" void kernel_launch(void* const* d_in, const int* in_sizes, int n_in,
                              void* d_out, int out_size)
{
    const float* x  = (const float*)d_in[0];
    const float* w0 = (const float*)d_in[1];
    const float* b0 = (const float*)d_in[2];
    const float* w1 = (const float*)d_in[3];
    const float* b1 = (const float*)d_in[4];
    const float* w2 = (const float*)d_in[5];
    const float* b2 = (const float*)d_in[6];
    const float* w3 = (const float*)d_in[7];
    const float* b3 = (const float*)d_in[8];
    const float* wf = (const float*)d_in[9];
    const float* bf = (const float*)d_in[10];
    float* out = (float*)d_out;

    float *px0, *pout1, *pout2, *pmean, *px2;
    uint32_t *pbpA, *pbpF;
    uint2 *pbp3;
    cudaGetSymbolAddress((void**)&px0,   g_x0);
    cudaGetSymbolAddress((void**)&pout1, g_out1);
    cudaGetSymbolAddress((void**)&pout2, g_out2);
    cudaGetSymbolAddress((void**)&pmean, g_mean);
    cudaGetSymbolAddress((void**)&px2,   g_x2);
    cudaGetSymbolAddress((void**)&pbpA,  g_bpA);
    cudaGetSymbolAddress((void**)&pbpF,  g_bpF);
    cudaGetSymbolAddress((void**)&pbp3,  g_bp3);

    cudaFuncSetAttribute(conv3x3_wmma,
                         cudaFuncAttributeMaxDynamicSharedMemorySize, CONV_SMEM);
    cudaFuncSetAttribute(dynconv_tap,
                         cudaFuncAttributeMaxDynamicSharedMemorySize, DYN_SMEM);

    // 0) weight permutations
    wconv_prep<<<(BPW_U32 + 255) / 256, 256>>>(w0, pbpA);
    wconv_prep<<<(BPW_U32 + 255) / 256, 256>>>(wf, pbpF);
    w3_prep_frag<<<(BP3_N + 255) / 256, 256>>>(w3, pbp3);
    // 1) conv0 on tensor cores
    conv3x3_wmma<<<dim3(HH, BN), 256, CONV_SMEM>>>(x, pbpA, b0, nullptr, px0, 0);
    // 2) per-channel spatial mean
    mean_kernel<<<BN * CC, 256>>>(px0, pmean);
    // 3) ECA conv1d over channel axis
    eca_kernel<<<1, BN * CC>>>(pmean, w2, b2, px2);
    // 4) depthwise + channel attention
    dw_kernel<<<dim3(HH / 8, CC, BN), 256>>>(px0, w1, b1, px2, pout1);
    // 5) dynamic conv: per-tap GEMMs, register-fused apply
    dynconv_tap<<<dim3(HH, BN), 256, DYN_SMEM>>>(pout1, px0, pbp3, b3, pout2);
    // 6) final conv on tensor cores + residual
    conv3x3_wmma<<<dim3(HH, BN), 256, CONV_SMEM>>>(pout2, pbpF, bf, x, out, 1);
}

// round 10
// speedup vs baseline: 2.5259x; 1.1166x over previous
#include <cuda_runtime.h>
#include <cuda_bf16.h>
#include <cstdint>

// Problem constants
#define BN 8
#define CC 64
#define HH 128
#define WW 128
#define NPIX (HH * WW)

// ---------------------------------------------------------------------------
// mma.sync m16n8k16 bf16 (baseline ISA; fragment layout validated R6/R7)
// ---------------------------------------------------------------------------
__device__ __forceinline__ void mma16816(float& d0, float& d1, float& d2, float& d3,
                                         uint32_t a0, uint32_t a1, uint32_t a2, uint32_t a3,
                                         uint32_t b0, uint32_t b1) {
    asm volatile(
        "mma.sync.aligned.m16n8k16.row.col.f32.bf16.bf16.f32 "
        "{%0,%1,%2,%3}, {%4,%5,%6,%7}, {%8,%9}, {%0,%1,%2,%3};"
        : "+f"(d0), "+f"(d1), "+f"(d2), "+f"(d3)
        : "r"(a0), "r"(a1), "r"(a2), "r"(a3), "r"(b0), "r"(b1));
}

// ---------------------------------------------------------------------------
// Scratch
// ---------------------------------------------------------------------------
__device__ float g_x0[BN * CC * NPIX];
__device__ float g_out1[BN * CC * NPIX];
__device__ float g_out2[BN * CC * NPIX];
__device__ float g_mean[BN * CC];
__device__ float g_x2[BN * CC];
// Permuted dense-conv weights, hi/lo interleaved:
// uint4[(stage*18 + t)*8*32 + n*32 + lane] = (bh0, bh1, bl0, bl1)
#define BPW_U32 (2 * 18 * 8 * 32 * 4)
__device__ uint32_t g_bpA[BPW_U32];   // w0
__device__ uint32_t g_bpF[BPW_U32];   // wf
// Permuted W3 fragments, hi/lo interleaved:
// uint4[((k*2+hf)*16 + n*4 + ks)*32 + lane] = (bh0, bh1, bl0, bl1)
#define BP3_U32 (9 * 2 * 4 * 4 * 32 * 4)
__device__ uint32_t g_bp3[BP3_U32];

// ---------------------------------------------------------------------------
// Dense-conv weight permutation (hi/lo interleaved in uint4)
// ---------------------------------------------------------------------------
__global__ __launch_bounds__(256) void wconv_prep(const float* __restrict__ w,
                                                  uint32_t* __restrict__ bp)
{
    int idx = blockIdx.x * 256 + threadIdx.x;   // over BPW_U32 u32 slots
    if (idx >= BPW_U32) return;
    int word  = idx & 3;            // 0,1 = hi reg0/1; 2,3 = lo reg0/1
    int lane  = (idx >> 2) & 31;
    int nt    = (idx >> 7) & 7;
    int r     = idx >> 10;          // stage*18 + t
    int t     = r % 18;
    int stage = r / 18;
    int split = word >> 1;
    int reg   = word & 1;

    int tap = t >> 1;
    int icb = (t & 1) << 4;
    int tg  = lane & 3;
    int g   = lane >> 2;
    int ic  = stage * 32 + icb + 2 * tg + (reg ? 8 : 0);
    int oc  = nt * 8 + g;

    float v0 = w[(oc * CC + ic) * 9 + tap];
    float v1 = w[(oc * CC + ic + 1) * 9 + tap];
    __nv_bfloat16 h0 = __float2bfloat16(v0);
    __nv_bfloat16 h1 = __float2bfloat16(v1);
    __nv_bfloat16 e0, e1;
    if (split == 0) { e0 = h0; e1 = h1; }
    else {
        e0 = __float2bfloat16(v0 - __bfloat162float(h0));
        e1 = __float2bfloat16(v1 - __bfloat162float(h1));
    }
    __nv_bfloat162 p(e0, e1);
    bp[idx] = *(uint32_t*)&p;
}

// ---------------------------------------------------------------------------
// W3 fragment permutation (hi/lo interleaved in uint4)
// ---------------------------------------------------------------------------
__global__ __launch_bounds__(256) void w3_prep_frag(const float* __restrict__ w3,
                                                    uint32_t* __restrict__ bp)
{
    int idx = blockIdx.x * 256 + threadIdx.x;
    if (idx >= BP3_U32) return;
    int word = idx & 3;
    int lane = (idx >> 2) & 31;
    int t = idx >> 7;
    int ks = t & 3;  t >>= 2;
    int nt = t & 3;  t >>= 2;
    int hf = t & 1;  t >>= 1;
    int k  = t;                      // 0..8
    int split = word >> 1;
    int r     = word & 1;

    int g  = lane >> 2;
    int tg = lane & 3;
    int cout = hf * 32 + nt * 8 + g;
    const float* row = w3 + (long)(cout * 9 + k) * 64;

    int kk = 16 * ks + 2 * tg + (r ? 8 : 0);
    float v0 = row[kk];
    float v1 = row[kk + 1];
    __nv_bfloat16 h0 = __float2bfloat16(v0);
    __nv_bfloat16 h1 = __float2bfloat16(v1);
    __nv_bfloat16 e0, e1;
    if (split == 0) { e0 = h0; e1 = h1; }
    else {
        e0 = __float2bfloat16(v0 - __bfloat162float(h0));
        e1 = __float2bfloat16(v1 - __bfloat162float(h1));
    }
    __nv_bfloat162 p(e0, e1);
    bp[idx] = *(uint32_t*)&p;
}

// ---------------------------------------------------------------------------
// Dense 3x3 conv via mma.sync bf16 hi/lo implicit GEMM.
//   CPAD=36, launch_bounds(256,4): 4 CTAs/SM. B via LDG.128 (hi+lo fused).
// ---------------------------------------------------------------------------
#define CPAD 36
#define SELEM (3 * 130 * CPAD)
#define CONV_SMEM (2 * SELEM * 2)

__global__ __launch_bounds__(256, 4) void conv3x3_wmma(
    const float* __restrict__ in, const uint32_t* __restrict__ bp,
    const float* __restrict__ bias, const float* __restrict__ res,
    float* __restrict__ outp, int add_res)
{
    extern __shared__ __align__(16) char smem[];
    __nv_bfloat16* Shi = (__nv_bfloat16*)smem;
    __nv_bfloat16* Slo = Shi + SELEM;

    const int tid  = threadIdx.x;
    const int warp = tid >> 5;
    const int lane = tid & 31;
    const int g    = lane >> 2;
    const int tg   = lane & 3;
    const int m0   = warp * 16;
    const int h = blockIdx.x;
    const int b = blockIdx.y;

    // hoisted halo coordinates (elements e = dy*130 + j)
    const int e0 = tid, e1 = tid + 256;
    int gh0 = h - 1 + e0 / 130, gw0 = e0 % 130 - 1;
    int gh1 = h - 1 + e1 / 130, gw1 = e1 % 130 - 1;
    const bool a0v = (unsigned)gh0 < (unsigned)HH && (unsigned)gw0 < (unsigned)WW;
    const bool a1v = (e1 < 390) && (unsigned)gh1 < (unsigned)HH && (unsigned)gw1 < (unsigned)WW;
    const long go0 = (long)gh0 * WW + gw0;
    const long go1 = (long)gh1 * WW + gw1;

    float d[8][4];
#pragma unroll
    for (int n = 0; n < 8; n++)
#pragma unroll
        for (int r = 0; r < 4; r++) d[n][r] = 0.f;

    for (int stage = 0; stage < 2; stage++) {
        if (stage) __syncthreads();

        const int cs = stage * 32;
        const float* pl = in + (long)(b * CC + cs) * NPIX;
#pragma unroll 4
        for (int c2 = 0; c2 < 16; c2++) {
            float f00 = a0v ? pl[go0] : 0.f;
            float f10 = a0v ? pl[NPIX + go0] : 0.f;
            __nv_bfloat16 h00 = __float2bfloat16(f00);
            __nv_bfloat16 h10 = __float2bfloat16(f10);
            __nv_bfloat16 l00 = __float2bfloat16(f00 - __bfloat162float(h00));
            __nv_bfloat16 l10 = __float2bfloat16(f10 - __bfloat162float(h10));
            __nv_bfloat162 ph0(h00, h10), pl0(l00, l10);
            *(uint32_t*)&Shi[e0 * CPAD + 2 * c2] = *(uint32_t*)&ph0;
            *(uint32_t*)&Slo[e0 * CPAD + 2 * c2] = *(uint32_t*)&pl0;
            if (e1 < 390) {
                float f01 = a1v ? pl[go1] : 0.f;
                float f11 = a1v ? pl[NPIX + go1] : 0.f;
                __nv_bfloat16 h01 = __float2bfloat16(f01);
                __nv_bfloat16 h11 = __float2bfloat16(f11);
                __nv_bfloat16 l01 = __float2bfloat16(f01 - __bfloat162float(h01));
                __nv_bfloat16 l11 = __float2bfloat16(f11 - __bfloat162float(h11));
                __nv_bfloat162 ph1(h01, h11), pl1(l01, l11);
                *(uint32_t*)&Shi[e1 * CPAD + 2 * c2] = *(uint32_t*)&ph1;
                *(uint32_t*)&Slo[e1 * CPAD + 2 * c2] = *(uint32_t*)&pl1;
            }
            pl += 2 * NPIX;
        }
        __syncthreads();

        const uint4* Bq = (const uint4*)bp + (size_t)(stage * 18) * 256;
#pragma unroll 3
        for (int t = 0; t < 18; t++) {
            const int tap = t >> 1;
            const int icb = (t & 1) << 4;
            const int ky = tap / 3, kx = tap - 3 * ky;
            const int be = (ky * 130 + m0 + g + kx) * CPAD + icb + 2 * tg;
            uint32_t ah0 = *(const uint32_t*)&Shi[be];
            uint32_t ah1 = *(const uint32_t*)&Shi[be + 8 * CPAD];
            uint32_t ah2 = *(const uint32_t*)&Shi[be + 8];
            uint32_t ah3 = *(const uint32_t*)&Shi[be + 8 * CPAD + 8];
            uint32_t al0 = *(const uint32_t*)&Slo[be];
            uint32_t al1 = *(const uint32_t*)&Slo[be + 8 * CPAD];
            uint32_t al2 = *(const uint32_t*)&Slo[be + 8];
            uint32_t al3 = *(const uint32_t*)&Slo[be + 8 * CPAD + 8];
            const uint4* br = Bq + t * 256 + lane;
#pragma unroll
            for (int n = 0; n < 8; n++) {
                uint4 bq = br[n * 32];   // (bh0, bh1, bl0, bl1)
                mma16816(d[n][0], d[n][1], d[n][2], d[n][3],
                         ah0, ah1, ah2, ah3, bq.x, bq.y);
                mma16816(d[n][0], d[n][1], d[n][2], d[n][3],
                         ah0, ah1, ah2, ah3, bq.z, bq.w);
                mma16816(d[n][0], d[n][1], d[n][2], d[n][3],
                         al0, al1, al2, al3, bq.x, bq.y);
            }
        }
    }

    const int p0 = m0 + g;
    const int p1 = p0 + 8;
#pragma unroll
    for (int n = 0; n < 8; n++) {
        const int oc = n * 8 + 2 * tg;
        const float b0v = bias[oc];
        const float b1v = bias[oc + 1];
        long base0 = ((long)(b * CC + oc) * HH + h) * WW;
        long base1 = base0 + (long)HH * WW;
        float v00 = d[n][0] + b0v;
        float v01 = d[n][1] + b1v;
        float v10 = d[n][2] + b0v;
        float v11 = d[n][3] + b1v;
        if (add_res) {
            v00 += res[base0 + p0]; v01 += res[base1 + p0];
            v10 += res[base0 + p1]; v11 += res[base1 + p1];
        }
        outp[base0 + p0] = v00;
        outp[base1 + p0] = v01;
        outp[base0 + p1] = v10;
        outp[base1 + p1] = v11;
    }
}

// ---------------------------------------------------------------------------
// mean / eca / dw (unchanged)
// ---------------------------------------------------------------------------
__global__ __launch_bounds__(256) void mean_kernel(const float* __restrict__ x0,
                                                   float* __restrict__ mean)
{
    const int bc = blockIdx.x;
    const float4* p4 = (const float4*)(x0 + (long)bc * NPIX);
    float s = 0.f;
    for (int i = threadIdx.x; i < NPIX / 4; i += 256) {
        float4 v = p4[i];
        s += v.x + v.y + v.z + v.w;
    }
    __shared__ float red[256];
    red[threadIdx.x] = s;
    __syncthreads();
    for (int off = 128; off > 0; off >>= 1) {
        if (threadIdx.x < off) red[threadIdx.x] += red[threadIdx.x + off];
        __syncthreads();
    }
    if (threadIdx.x == 0) mean[bc] = red[0] * (1.f / (float)NPIX);
}

__global__ void eca_kernel(const float* __restrict__ mean,
                           const float* __restrict__ w2,
                           const float* __restrict__ b2,
                           float* __restrict__ x2o)
{
    const int t = threadIdx.x;
    const int b = t >> 6, c = t & 63;
    float m0 = (c > 0)  ? mean[b * CC + c - 1] : 0.f;
    float m1 =            mean[b * CC + c];
    float m2 = (c < 63) ? mean[b * CC + c + 1] : 0.f;
    x2o[t] = w2[0] * m0 + w2[1] * m1 + w2[2] * m2 + b2[0];
}

__global__ __launch_bounds__(256) void dw_kernel(
    const float* __restrict__ x0, const float* __restrict__ w1,
    const float* __restrict__ b1, const float* __restrict__ x2,
    float* __restrict__ outp)
{
    __shared__ float t[10][130];
    const int h0 = blockIdx.x * 8;
    const int c  = blockIdx.y;
    const int b  = blockIdx.z;
    const float* src = x0 + (long)(b * CC + c) * NPIX;

    for (int i = threadIdx.x; i < 10 * 130; i += 256) {
        int r = i / 130, col = i % 130;
        int gh = h0 - 1 + r, gw = col - 1;
        float v = 0.f;
        if ((unsigned)gh < (unsigned)HH && (unsigned)gw < (unsigned)WW)
            v = src[gh * WW + gw];
        t[r][col] = v;
    }
    float wk[9];
#pragma unroll
    for (int k = 0; k < 9; k++) wk[k] = w1[c * 9 + k];
    const float bb = b1[c] + x2[b * CC + c];
    __syncthreads();

    float* dst = outp + (long)(b * CC + c) * NPIX + (long)h0 * WW;
    for (int p = threadIdx.x; p < 8 * WW; p += 256) {
        int r = p / WW, wc = p % WW;
        float a = bb;
#pragma unroll
        for (int dy = 0; dy < 3; dy++)
#pragma unroll
            for (int dx = 0; dx < 3; dx++)
                a += wk[dy * 3 + dx] * t[r + dy][wc + dx];
        dst[p] = a;
    }
}

// ---------------------------------------------------------------------------
// Dynamic conv via per-tap GEMMs with smem aliasing + LDG.128 B loads.
// ---------------------------------------------------------------------------
#define APITCH 72
#define DOFF_B3  50688
#define DYN_SMEM (50688 + 2304)

__global__ __launch_bounds__(256, 3) void dynconv_tap(
    const float* __restrict__ out1, const float* __restrict__ x0,
    const uint32_t* __restrict__ bp3, const float* __restrict__ b3,
    float* __restrict__ out2)
{
    extern __shared__ __align__(16) char smem[];
    __nv_bfloat16* Ahi = (__nv_bfloat16*)smem;           // [0, 18432)
    __nv_bfloat16* Alo = Ahi + 128 * APITCH;             // [18432, 36864)
    float* x0s = (float*)smem;                           // aliases A region
    float* b3s = (float*)(smem + DOFF_B3);

    const int tid  = threadIdx.x;
    const int warp = tid >> 5;
    const int lane = tid & 31;
    const int g    = lane >> 2;
    const int tg   = lane & 3;
    const int m0   = warp * 16;
    const int h = blockIdx.x;
    const int b = blockIdx.y;

    // ---- stage A: out1[b,:,h,:] -> [p][c] bf16 hi/lo -----------------------
    {
        const long base = (long)b * CC * NPIX + (long)h * WW;
        for (int i = tid; i < 128 * 32; i += 256) {
            int p  = i >> 5;
            int cp = i & 31;
            float v0 = out1[base + (long)(2 * cp)     * NPIX + p];
            float v1 = out1[base + (long)(2 * cp + 1) * NPIX + p];
            __nv_bfloat16 h0 = __float2bfloat16(v0);
            __nv_bfloat16 h1 = __float2bfloat16(v1);
            __nv_bfloat16 l0 = __float2bfloat16(v0 - __bfloat162float(h0));
            __nv_bfloat16 l1 = __float2bfloat16(v1 - __bfloat162float(h1));
            __nv_bfloat162 ph(h0, h1), plp(l0, l1);
            *(uint32_t*)&Ahi[p * APITCH + 2 * cp] = *(uint32_t*)&ph;
            *(uint32_t*)&Alo[p * APITCH + 2 * cp] = *(uint32_t*)&plp;
        }
        for (int i = tid; i < 576; i += 256) b3s[i] = b3[i];
    }
    __syncthreads();

    // ---- A fragments in registers -----------------------------------------
    uint32_t Ah[4][4], Al[4][4];
#pragma unroll
    for (int k = 0; k < 4; k++) {
        int col = k * 16 + tg * 2;
        Ah[k][0] = *(const uint32_t*)&Ahi[(m0 + g)     * APITCH + col];
        Ah[k][1] = *(const uint32_t*)&Ahi[(m0 + g + 8) * APITCH + col];
        Ah[k][2] = *(const uint32_t*)&Ahi[(m0 + g)     * APITCH + col + 8];
        Ah[k][3] = *(const uint32_t*)&Ahi[(m0 + g + 8) * APITCH + col + 8];
        Al[k][0] = *(const uint32_t*)&Alo[(m0 + g)     * APITCH + col];
        Al[k][1] = *(const uint32_t*)&Alo[(m0 + g + 8) * APITCH + col];
        Al[k][2] = *(const uint32_t*)&Alo[(m0 + g)     * APITCH + col + 8];
        Al[k][3] = *(const uint32_t*)&Alo[(m0 + g + 8) * APITCH + col + 8];
    }

    const int p0 = m0 + g;
    const int p1 = p0 + 8;

    for (int hf = 0; hf < 2; hf++) {
        const int cbase = hf * 32;
        __syncthreads();   // fragments loaded / previous half done with x0s
        // ---- stage x0 halo for this half: [3][32][132] (overwrites A) -----
        for (int i = tid; i < 3 * 32 * 132; i += 256) {
            int dy = i / (32 * 132);
            int r  = i - dy * (32 * 132);
            int c  = r / 132;
            int j  = r - c * 132;
            int gh = h - 1 + dy, gw = j - 1;
            float v = 0.f;
            if ((unsigned)gh < (unsigned)HH && (unsigned)gw < (unsigned)WW)
                v = x0[((long)(b * CC + cbase + c) * HH + gh) * WW + gw];
            x0s[i] = v;
        }
        __syncthreads();

        float acc[4][4];
#pragma unroll
        for (int n = 0; n < 4; n++)
#pragma unroll
            for (int r = 0; r < 4; r++) acc[n][r] = 0.f;

#pragma unroll
        for (int k = 0; k < 9; k++) {
            const int dy = k / 3, dx = k - 3 * dy;
            const uint4* Bq = (const uint4*)bp3 + (size_t)(k * 2 + hf) * 512 + lane;
#pragma unroll
            for (int n = 0; n < 4; n++) {
                float d0 = 0.f, d1 = 0.f, d2 = 0.f, d3 = 0.f;
#pragma unroll
                for (int ks = 0; ks < 4; ks++) {
                    uint4 bq = Bq[(n * 4 + ks) * 32];   // (bh0, bh1, bl0, bl1)
                    mma16816(d0, d1, d2, d3, Ah[ks][0], Ah[ks][1], Ah[ks][2], Ah[ks][3], bq.x, bq.y);
                    mma16816(d0, d1, d2, d3, Ah[ks][0], Ah[ks][1], Ah[ks][2], Ah[ks][3], bq.z, bq.w);
                    mma16816(d0, d1, d2, d3, Al[ks][0], Al[ks][1], Al[ks][2], Al[ks][3], bq.x, bq.y);
                }
                const int cl = n * 8 + 2 * tg;
                const float bb0 = b3s[(cbase + cl) * 9 + k];
                const float bb1 = b3s[(cbase + cl + 1) * 9 + k];
                const float* xr0 = &x0s[(dy * 32 + cl) * 132];
                const float* xr1 = xr0 + 132;
                acc[n][0] += (d0 + bb0) * xr0[p0 + dx];
                acc[n][1] += (d1 + bb1) * xr1[p0 + dx];
                acc[n][2] += (d2 + bb0) * xr0[p1 + dx];
                acc[n][3] += (d3 + bb1) * xr1[p1 + dx];
            }
        }

#pragma unroll
        for (int n = 0; n < 4; n++) {
            const int c = cbase + n * 8 + 2 * tg;
            long base0 = ((long)(b * CC + c) * HH + h) * WW;
            long base1 = base0 + (long)HH * WW;
            float v00 = acc[n][0], v01 = acc[n][1], v10 = acc[n][2], v11 = acc[n][3];
            v00 = (v00 >= 0.f) ? v00 : 0.2f * v00;
            v01 = (v01 >= 0.f) ? v01 : 0.2f * v01;
            v10 = (v10 >= 0.f) ? v10 : 0.2f * v10;
            v11 = (v11 >= 0.f) ? v11 : 0.2f * v11;
            out2[base0 + p0] = v00;
            out2[base1 + p0] = v01;
            out2[base0 + p1] = v10;
            out2[base1 + p1] = v11;
        }
    }
}

// ---------------------------------------------------------------------------
// Launch
// ---------------------------------------------------------------------------
extern "C" void kernel_launch(void* const* d_in, const int* in_sizes, int n_in,
                              void* d_out, int out_size)
{
    const float* x  = (const float*)d_in[0];
    const float* w0 = (const float*)d_in[1];
    const float* b0 = (const float*)d_in[2];
    const float* w1 = (const float*)d_in[3];
    const float* b1 = (const float*)d_in[4];
    const float* w2 = (const float*)d_in[5];
    const float* b2 = (const float*)d_in[6];
    const float* w3 = (const float*)d_in[7];
    const float* b3 = (const float*)d_in[8];
    const float* wf = (const float*)d_in[9];
    const float* bf = (const float*)d_in[10];
    float* out = (float*)d_out;

    float *px0, *pout1, *pout2, *pmean, *px2;
    uint32_t *pbpA, *pbpF, *pbp3;
    cudaGetSymbolAddress((void**)&px0,   g_x0);
    cudaGetSymbolAddress((void**)&pout1, g_out1);
    cudaGetSymbolAddress((void**)&pout2, g_out2);
    cudaGetSymbolAddress((void**)&pmean, g_mean);
    cudaGetSymbolAddress((void**)&px2,   g_x2);
    cudaGetSymbolAddress((void**)&pbpA,  g_bpA);
    cudaGetSymbolAddress((void**)&pbpF,  g_bpF);
    cudaGetSymbolAddress((void**)&pbp3,  g_bp3);

    cudaFuncSetAttribute(conv3x3_wmma,
                         cudaFuncAttributeMaxDynamicSharedMemorySize, CONV_SMEM);
    cudaFuncSetAttribute(dynconv_tap,
                         cudaFuncAttributeMaxDynamicSharedMemorySize, DYN_SMEM);

    // 0) weight permutations
    wconv_prep<<<(BPW_U32 + 255) / 256, 256>>>(w0, pbpA);
    wconv_prep<<<(BPW_U32 + 255) / 256, 256>>>(wf, pbpF);
    w3_prep_frag<<<(BP3_U32 + 255) / 256, 256>>>(w3, pbp3);
    // 1) conv0 on tensor cores
    conv3x3_wmma<<<dim3(HH, BN), 256, CONV_SMEM>>>(x, pbpA, b0, nullptr, px0, 0);
    // 2) per-channel spatial mean
    mean_kernel<<<BN * CC, 256>>>(px0, pmean);
    // 3) ECA conv1d over channel axis
    eca_kernel<<<1, BN * CC>>>(pmean, w2, b2, px2);
    // 4) depthwise + channel attention
    dw_kernel<<<dim3(HH / 8, CC, BN), 256>>>(px0, w1, b1, px2, pout1);
    // 5) dynamic conv: per-tap GEMMs, register-fused apply
    dynconv_tap<<<dim3(HH, BN), 256, DYN_SMEM>>>(pout1, px0, pbp3, b3, pout2);
    // 6) final conv on tensor cores + residual
    conv3x3_wmma<<<dim3(HH, BN), 256, CONV_SMEM>>>(pout2, pbpF, bf, x, out, 1);
}